// round 1
// baseline (speedup 1.0000x reference)
#include <cuda_runtime.h>
#include <math.h>

#define BB 4
#define TT 512
#define SS 1024
#define HH 1024
#define FF 4096
#define NHH 16
#define DHD 64
#define LL 6

// ---------------- scratch (device globals; no runtime allocation) ----------------
__device__ float g_x[BB*TT*HH];        // residual stream
__device__ float g_h[BB*TT*HH];        // layernorm output
__device__ float g_q[BB*TT*HH];
__device__ float g_k[BB*SS*HH];
__device__ float g_v[BB*SS*HH];
__device__ float g_ctx[BB*TT*HH];
__device__ float g_scores[(size_t)BB*NHH*TT*SS];
__device__ float g_ffn[BB*TT*FF];
__device__ float g_pe[TT*HH];
__device__ double g_invf[HH];
__device__ float g_wt[HH];

// ---------------- small helpers ----------------
__device__ __forceinline__ float block_reduce_sum(float v, float* red) {
    int tid = threadIdx.x;
    red[tid] = v; __syncthreads();
    for (int s = 128; s > 0; s >>= 1) {
        if (tid < s) red[tid] += red[tid + s];
        __syncthreads();
    }
    float r = red[0]; __syncthreads();
    return r;
}

// ---------------- embedding / positional ----------------
__global__ void invfreq_kernel() {
    int h = blockIdx.x * blockDim.x + threadIdx.x;
    if (h < HH) {
        double e = (double)(2 * (h / 2)) / (double)HH;
        g_invf[h] = pow(10000.0, -e);
    }
}

__global__ void pe_kernel() {
    int idx = blockIdx.x * blockDim.x + threadIdx.x;  // T*H
    int t = idx / HH, h = idx % HH;
    double ang = (double)t * g_invf[h];
    g_pe[idx] = (float)((h & 1) ? cos(ang) : sin(ang));
}

__global__ void embed_kernel(const int* __restrict__ tgt, const float* __restrict__ emb) {
    long idx = (long)blockIdx.x * blockDim.x + threadIdx.x;  // B*T*H
    int h = (int)(idx % HH);
    long bt = idx / HH;
    int tok = tgt[bt];
    int t = (int)(bt % TT);
    g_x[idx] = emb[(long)tok * HH + h] * 32.0f + g_pe[t * HH + h];
}

// ---------------- layernorm ----------------
__global__ void ln_kernel(const float* __restrict__ X, const float* __restrict__ g,
                          const float* __restrict__ b, float* __restrict__ Y) {
    __shared__ float red[256];
    long row = blockIdx.x;
    const float* x = X + row * HH;
    float* y = Y + row * HH;
    int tid = threadIdx.x;
    float s = 0.f;
    for (int i = tid; i < HH; i += 256) s += x[i];
    float mean = block_reduce_sum(s, red) * (1.0f / HH);
    float v = 0.f;
    for (int i = tid; i < HH; i += 256) { float d = x[i] - mean; v += d * d; }
    float var = block_reduce_sum(v, red) * (1.0f / HH);
    float inv = 1.0f / sqrtf(var + 1e-6f);
    for (int i = tid; i < HH; i += 256)
        y[i] = (x[i] - mean) * inv * g[i] + b[i];
}

// ---------------- generic fp32 GEMM: C = A(MxK) @ B(KxN) [+bias][+res][relu] ----------------
// flags: 1 = bias, 2 = residual, 4 = relu
__global__ void gemm64(const float* __restrict__ A, const float* __restrict__ Bm,
                       const float* __restrict__ bias, const float* __restrict__ res,
                       float* __restrict__ C, int M, int N, int K, int flags) {
    __shared__ float As[16][65];
    __shared__ float Bs[16][64];
    int tid = threadIdx.x;
    int tx = tid & 15, ty = tid >> 4;
    int m0 = blockIdx.y * 64, n0 = blockIdx.x * 64;
    float acc[4][4] = {};
    for (int k0 = 0; k0 < K; k0 += 16) {
        #pragma unroll
        for (int i = 0; i < 4; i++) {
            int idx = tid + i * 256;
            int r = idx >> 4, c = idx & 15;
            As[c][r] = A[(long)(m0 + r) * K + (k0 + c)];
        }
        #pragma unroll
        for (int i = 0; i < 4; i++) {
            int idx = tid + i * 256;
            int r = idx >> 6, c = idx & 63;
            Bs[r][c] = Bm[(long)(k0 + r) * N + (n0 + c)];
        }
        __syncthreads();
        #pragma unroll
        for (int kk = 0; kk < 16; kk++) {
            float a[4], bb[4];
            #pragma unroll
            for (int i = 0; i < 4; i++) a[i] = As[kk][ty * 4 + i];
            #pragma unroll
            for (int j = 0; j < 4; j++) bb[j] = Bs[kk][tx * 4 + j];
            #pragma unroll
            for (int i = 0; i < 4; i++)
                #pragma unroll
                for (int j = 0; j < 4; j++)
                    acc[i][j] += a[i] * bb[j];
        }
        __syncthreads();
    }
    #pragma unroll
    for (int i = 0; i < 4; i++) {
        int m = m0 + ty * 4 + i;
        #pragma unroll
        for (int j = 0; j < 4; j++) {
            int n = n0 + tx * 4 + j;
            float v = acc[i][j];
            if (flags & 1) v += bias[n];
            if (flags & 2) v += res[(long)m * N + n];
            if (flags & 4) v = fmaxf(v, 0.f);
            C[(long)m * N + n] = v;
        }
    }
}

// ---------------- attention scores: S[bh,t,s] = (q . k)/8, masked ----------------
__global__ void scores_kernel(const float* __restrict__ Q, const float* __restrict__ Km,
                              float* __restrict__ Sout, const unsigned char* __restrict__ pad,
                              int Tq, int Tk, int causal) {
    __shared__ float qs[64][65];
    __shared__ float ks[64][65];
    int bh = blockIdx.z;
    int b = bh / NHH, h = bh % NHH;
    int t0 = blockIdx.y * 64, s0 = blockIdx.x * 64;
    int tid = threadIdx.x;
    const float* Qb = Q + ((long)(b * Tq + t0)) * HH + h * DHD;
    const float* Kb = Km + ((long)(b * Tk + s0)) * HH + h * DHD;
    #pragma unroll
    for (int i = 0; i < 16; i++) {
        int idx = tid + i * 256;
        int r = idx >> 6, c = idx & 63;
        qs[r][c] = Qb[(long)r * HH + c];
        ks[r][c] = Kb[(long)r * HH + c];
    }
    __syncthreads();
    int tx = tid & 15, ty = tid >> 4;
    float acc[4][4] = {};
    #pragma unroll 8
    for (int d = 0; d < 64; d++) {
        float a[4], bb[4];
        #pragma unroll
        for (int i = 0; i < 4; i++) a[i] = qs[ty * 4 + i][d];
        #pragma unroll
        for (int j = 0; j < 4; j++) bb[j] = ks[tx * 4 + j][d];
        #pragma unroll
        for (int i = 0; i < 4; i++)
            #pragma unroll
            for (int j = 0; j < 4; j++)
                acc[i][j] += a[i] * bb[j];
    }
    #pragma unroll
    for (int i = 0; i < 4; i++) {
        int t = t0 + ty * 4 + i;
        #pragma unroll
        for (int j = 0; j < 4; j++) {
            int s = s0 + tx * 4 + j;
            float v = acc[i][j] * 0.125f;
            bool m = (causal && (s > t)) || (pad[(long)b * Tk + s] != 0);
            Sout[((long)bh * Tq + t) * Tk + s] = m ? -1e18f : v;
        }
    }
}

// ---------------- softmax over last dim, in place ----------------
__global__ void softmax_kernel(float* __restrict__ Sc, int Tk) {
    __shared__ float red[256];
    long row = blockIdx.x;
    float* p = Sc + row * Tk;
    int tid = threadIdx.x;
    float mx = -3.0e38f;
    for (int i = tid; i < Tk; i += 256) mx = fmaxf(mx, p[i]);
    red[tid] = mx; __syncthreads();
    for (int s = 128; s > 0; s >>= 1) {
        if (tid < s) red[tid] = fmaxf(red[tid], red[tid + s]);
        __syncthreads();
    }
    mx = red[0]; __syncthreads();
    float sum = 0.f;
    for (int i = tid; i < Tk; i += 256) {
        float e = expf(p[i] - mx);
        p[i] = e;
        sum += e;
    }
    float tot = block_reduce_sum(sum, red);
    float inv = 1.0f / tot;
    for (int i = tid; i < Tk; i += 256) p[i] *= inv;
}

// ---------------- ctx: C[bh][t][d] = sum_s W[t,s] * V[s,d], d=64 ----------------
__global__ void ctx_kernel(const float* __restrict__ W, const float* __restrict__ Vm,
                           float* __restrict__ C, int Tq, int Tk) {
    __shared__ float ws[64][17];
    __shared__ float vs[16][64];
    int bh = blockIdx.z, b = bh / NHH, h = bh % NHH;
    int t0 = blockIdx.y * 64;
    int tid = threadIdx.x, tx = tid & 15, ty = tid >> 4;
    const float* Wb = W + ((long)bh * Tq + t0) * Tk;
    const float* Vb = Vm + ((long)b * Tk) * HH + h * DHD;
    float acc[4][4] = {};
    for (int k0 = 0; k0 < Tk; k0 += 16) {
        #pragma unroll
        for (int i = 0; i < 4; i++) {
            int idx = tid + i * 256;
            int r = idx >> 4, c = idx & 15;
            ws[r][c] = Wb[(long)r * Tk + k0 + c];
        }
        {
            int r = tid >> 6, c = tid & 63;
            #pragma unroll
            for (int i = 0; i < 4; i++)
                vs[r + i * 4][c] = Vb[(long)(k0 + r + i * 4) * HH + c];
        }
        __syncthreads();
        #pragma unroll
        for (int kk = 0; kk < 16; kk++) {
            float a[4], bb[4];
            #pragma unroll
            for (int i = 0; i < 4; i++) a[i] = ws[ty * 4 + i][kk];
            #pragma unroll
            for (int j = 0; j < 4; j++) bb[j] = vs[kk][tx * 4 + j];
            #pragma unroll
            for (int i = 0; i < 4; i++)
                #pragma unroll
                for (int j = 0; j < 4; j++)
                    acc[i][j] += a[i] * bb[j];
        }
        __syncthreads();
    }
    #pragma unroll
    for (int i = 0; i < 4; i++) {
        int t = t0 + ty * 4 + i;
        #pragma unroll
        for (int j = 0; j < 4; j++)
            C[((long)(b * Tq) + t) * HH + h * DHD + tx * 4 + j] = acc[i][j];
    }
}

// ---------------- save residual stream into result2 (B,L,T,H) ----------------
__global__ void save_kernel(float* __restrict__ out_r2, int l) {
    long idx = (long)blockIdx.x * blockDim.x + threadIdx.x;  // B*T*H
    int h = (int)(idx % HH);
    long bt = idx / HH;
    int t = (int)(bt % TT);
    int b = (int)(bt / TT);
    out_r2[(((long)b * LL + l) * TT + t) * HH + h] = g_x[idx];
}

// ---------------- avg attention weights over heads (last cross layer) ----------------
__global__ void aw_kernel(float* __restrict__ out_ws) {
    long idx = (long)blockIdx.x * blockDim.x + threadIdx.x;  // B*T*S
    int s = (int)(idx % SS);
    long bt = idx / SS;
    int t = (int)(bt % TT);
    int b = (int)(bt / TT);
    float acc = 0.f;
    #pragma unroll
    for (int h = 0; h < NHH; h++)
        acc += g_scores[(((long)(b * NHH + h)) * TT + t) * SS + s];
    out_ws[idx] = acc * (1.0f / NHH);
}

// ---------------- p_trans head ----------------
__global__ void wt_kernel(const float* __restrict__ Wt1, const float* __restrict__ Wt2) {
    __shared__ float red[256];
    int i = blockIdx.x;
    float s = 0.f;
    for (int j = threadIdx.x; j < HH; j += 256)
        s += Wt1[(long)i * HH + j] * Wt2[j];
    float tot = block_reduce_sum(s, red);
    if (threadIdx.x == 0) g_wt[i] = tot;
}

__global__ void p_kernel(const float* __restrict__ X, float* __restrict__ outp) {
    __shared__ float red[256];
    long row = blockIdx.x;
    const float* xr = X + row * HH;
    float s = 0.f;
    for (int i = threadIdx.x; i < HH; i += 256) s += xr[i] * g_wt[i];
    float tot = block_reduce_sum(s, red);
    if (threadIdx.x == 0) outp[row] = 1.0f / (1.0f + expf(-tot));
}

// ---------------- driver ----------------
extern "C" void kernel_launch(void* const* d_in, const int* in_sizes, int n_in,
                              void* d_out, int out_size) {
    const int*            tgt      = (const int*)d_in[0];
    const unsigned char*  src_pad  = (const unsigned char*)d_in[1];
    const unsigned char*  tgt_pad  = (const unsigned char*)d_in[2];
    const float*          enc_out  = (const float*)d_in[3];
    const float*          emb      = (const float*)d_in[4];
    const float*          Wq_self  = (const float*)d_in[5];
    const float*          Wk_self  = (const float*)d_in[6];
    const float*          Wv_self  = (const float*)d_in[7];
    const float*          Wo_self  = (const float*)d_in[8];
    const float*          bo_self  = (const float*)d_in[9];
    const float*          Wq_src   = (const float*)d_in[10];
    const float*          Wk_src   = (const float*)d_in[11];
    const float*          Wv_src   = (const float*)d_in[12];
    const float*          Wo_src   = (const float*)d_in[13];
    const float*          bo_src   = (const float*)d_in[14];
    const float*          W1       = (const float*)d_in[15];
    const float*          W2       = (const float*)d_in[16];
    const float*          ln_g     = (const float*)d_in[17];
    const float*          ln_b     = (const float*)d_in[18];
    const float*          final_g  = (const float*)d_in[19];
    const float*          final_b  = (const float*)d_in[20];
    const float*          Wt1      = (const float*)d_in[21];
    const float*          Wt2      = (const float*)d_in[22];

    float* out    = (float*)d_out;
    float* out_r1 = out;                                    // (B,T,H)
    float* out_r2 = out + (size_t)BB * TT * HH;             // (B,L,T,H)
    float* out_p  = out_r2 + (size_t)BB * LL * TT * HH;     // (B,T,1)
    float* out_ws = out_p + (size_t)BB * TT;                // (B,T,S)

    float *x, *h, *q, *k, *v, *ctx, *sc, *ffn;
    cudaGetSymbolAddress((void**)&x,   g_x);
    cudaGetSymbolAddress((void**)&h,   g_h);
    cudaGetSymbolAddress((void**)&q,   g_q);
    cudaGetSymbolAddress((void**)&k,   g_k);
    cudaGetSymbolAddress((void**)&v,   g_v);
    cudaGetSymbolAddress((void**)&ctx, g_ctx);
    cudaGetSymbolAddress((void**)&sc,  g_scores);
    cudaGetSymbolAddress((void**)&ffn, g_ffn);

    const int MT = BB * TT;   // 2048
    const int MS = BB * SS;   // 4096

    invfreq_kernel<<<4, 256>>>();
    pe_kernel<<<TT * HH / 256, 256>>>();
    embed_kernel<<<BB * TT * HH / 256, 256>>>(tgt, emb);
    wt_kernel<<<HH, 256>>>(Wt1, Wt2);

    for (int l = 0; l < LL; l++) {
        // save residual stream at layer input
        save_kernel<<<BB * TT * HH / 256, 256>>>(out_r2, l);

        // --- self attention ---
        ln_kernel<<<MT, 256>>>(x, ln_g + (size_t)(l * 3 + 0) * HH, ln_b + (size_t)(l * 3 + 0) * HH, h);
        gemm64<<<dim3(HH / 64, MT / 64), 256>>>(h, Wq_self + (size_t)l * HH * HH, nullptr, nullptr, q, MT, HH, HH, 0);
        gemm64<<<dim3(HH / 64, MT / 64), 256>>>(h, Wk_self + (size_t)l * HH * HH, nullptr, nullptr, k, MT, HH, HH, 0);
        gemm64<<<dim3(HH / 64, MT / 64), 256>>>(h, Wv_self + (size_t)l * HH * HH, nullptr, nullptr, v, MT, HH, HH, 0);
        scores_kernel<<<dim3(TT / 64, TT / 64, BB * NHH), 256>>>(q, k, sc, tgt_pad, TT, TT, 1);
        softmax_kernel<<<BB * NHH * TT, 256>>>(sc, TT);
        ctx_kernel<<<dim3(1, TT / 64, BB * NHH), 256>>>(sc, v, ctx, TT, TT);
        gemm64<<<dim3(HH / 64, MT / 64), 256>>>(ctx, Wo_self + (size_t)l * HH * HH, bo_self + (size_t)l * HH, x, x, MT, HH, HH, 3);

        // --- cross attention ---
        ln_kernel<<<MT, 256>>>(x, ln_g + (size_t)(l * 3 + 1) * HH, ln_b + (size_t)(l * 3 + 1) * HH, h);
        gemm64<<<dim3(HH / 64, MT / 64), 256>>>(h, Wq_src + (size_t)l * HH * HH, nullptr, nullptr, q, MT, HH, HH, 0);
        gemm64<<<dim3(HH / 64, MS / 64), 256>>>(enc_out, Wk_src + (size_t)l * HH * HH, nullptr, nullptr, k, MS, HH, HH, 0);
        gemm64<<<dim3(HH / 64, MS / 64), 256>>>(enc_out, Wv_src + (size_t)l * HH * HH, nullptr, nullptr, v, MS, HH, HH, 0);
        scores_kernel<<<dim3(SS / 64, TT / 64, BB * NHH), 256>>>(q, k, sc, src_pad, TT, SS, 0);
        softmax_kernel<<<BB * NHH * TT, 256>>>(sc, SS);
        if (l == LL - 1)
            aw_kernel<<<BB * TT * SS / 256, 256>>>(out_ws);
        ctx_kernel<<<dim3(1, TT / 64, BB * NHH), 256>>>(sc, v, ctx, TT, SS);
        gemm64<<<dim3(HH / 64, MT / 64), 256>>>(ctx, Wo_src + (size_t)l * HH * HH, bo_src + (size_t)l * HH, x, x, MT, HH, HH, 3);

        // --- feed forward ---
        ln_kernel<<<MT, 256>>>(x, ln_g + (size_t)(l * 3 + 2) * HH, ln_b + (size_t)(l * 3 + 2) * HH, h);
        gemm64<<<dim3(FF / 64, MT / 64), 256>>>(h, W1 + (size_t)l * HH * FF, nullptr, nullptr, ffn, MT, FF, HH, 4);
        gemm64<<<dim3(HH / 64, MT / 64), 256>>>(ffn, W2 + (size_t)l * FF * HH, nullptr, x, x, MT, HH, FF, 2);
    }

    // outputs
    ln_kernel<<<MT, 256>>>(x, final_g, final_b, out_r1);
    p_kernel<<<MT, 256>>>(x, out_p);
}

// round 2
// speedup vs baseline: 2.2152x; 2.2152x over previous
#include <cuda_runtime.h>
#include <cuda_bf16.h>
#include <math.h>

#define BB 4
#define TT 512
#define SS 1024
#define HH 1024
#define FF 4096
#define NHH 16
#define DHD 64
#define LL 6
#define SPAD 34

// ---------------- scratch (device globals; no runtime allocation) ----------------
__device__ float g_x[BB*TT*HH];        // residual stream
__device__ float g_h[BB*TT*HH];        // layernorm output
__device__ float g_q[BB*TT*HH];
__device__ float g_k[BB*SS*HH];
__device__ float g_v[BB*SS*HH];
__device__ float g_ctx[BB*TT*HH];
__device__ float g_scores[(size_t)BB*NHH*TT*SS];
__device__ float g_ffn[BB*TT*FF];
__device__ float g_pe[TT*HH];
__device__ double g_invf[HH];
__device__ float g_wt[HH];

// ---------------- helpers ----------------
__device__ __forceinline__ float block_reduce_sum(float v, float* red) {
    int tid = threadIdx.x;
    red[tid] = v; __syncthreads();
    for (int s = 128; s > 0; s >>= 1) {
        if (tid < s) red[tid] += red[tid + s];
        __syncthreads();
    }
    float r = red[0]; __syncthreads();
    return r;
}

__device__ __forceinline__ void mma16816(float c[4], const unsigned a[4], const unsigned b[2]) {
    asm volatile("mma.sync.aligned.m16n8k16.row.col.f32.bf16.bf16.f32 "
        "{%0,%1,%2,%3}, {%4,%5,%6,%7}, {%8,%9}, {%0,%1,%2,%3};"
        : "+f"(c[0]), "+f"(c[1]), "+f"(c[2]), "+f"(c[3])
        : "r"(a[0]), "r"(a[1]), "r"(a[2]), "r"(a[3]), "r"(b[0]), "r"(b[1]));
}

#define U32AT(p) (*(const unsigned*)&(p))

// split fp32 pair into (hi,lo) bf16 pairs and store as bf162
__device__ __forceinline__ void split_store2(float x0, float x1,
                                             __nv_bfloat16* hp, __nv_bfloat16* lp) {
    __nv_bfloat16 h0 = __float2bfloat16(x0);
    __nv_bfloat16 h1 = __float2bfloat16(x1);
    __nv_bfloat16 l0 = __float2bfloat16(x0 - __bfloat162float(h0));
    __nv_bfloat16 l1 = __float2bfloat16(x1 - __bfloat162float(h1));
    *(__nv_bfloat162*)hp = __halves2bfloat162(h0, h1);
    *(__nv_bfloat162*)lp = __halves2bfloat162(l0, l1);
}

__device__ __forceinline__ void split1(float x, __nv_bfloat16& h, __nv_bfloat16& l) {
    h = __float2bfloat16(x);
    l = __float2bfloat16(x - __bfloat162float(h));
}

// ---------------- embedding / positional ----------------
__global__ void invfreq_kernel() {
    int h = blockIdx.x * blockDim.x + threadIdx.x;
    if (h < HH) {
        double e = (double)(2 * (h / 2)) / (double)HH;
        g_invf[h] = pow(10000.0, -e);
    }
}

__global__ void pe_kernel() {
    int idx = blockIdx.x * blockDim.x + threadIdx.x;
    int t = idx / HH, h = idx % HH;
    double ang = (double)t * g_invf[h];
    g_pe[idx] = (float)((h & 1) ? cos(ang) : sin(ang));
}

__global__ void embed_kernel(const int* __restrict__ tgt, const float* __restrict__ emb) {
    long idx = (long)blockIdx.x * blockDim.x + threadIdx.x;
    int h = (int)(idx % HH);
    long bt = idx / HH;
    int tok = tgt[bt];
    int t = (int)(bt % TT);
    g_x[idx] = emb[(long)tok * HH + h] * 32.0f + g_pe[t * HH + h];
}

// ---------------- layernorm ----------------
__global__ void ln_kernel(const float* __restrict__ X, const float* __restrict__ g,
                          const float* __restrict__ b, float* __restrict__ Y) {
    __shared__ float red[256];
    long row = blockIdx.x;
    const float* x = X + row * HH;
    float* y = Y + row * HH;
    int tid = threadIdx.x;
    float s = 0.f;
    for (int i = tid; i < HH; i += 256) s += x[i];
    float mean = block_reduce_sum(s, red) * (1.0f / HH);
    float v = 0.f;
    for (int i = tid; i < HH; i += 256) { float d = x[i] - mean; v += d * d; }
    float var = block_reduce_sum(v, red) * (1.0f / HH);
    float inv = 1.0f / sqrtf(var + 1e-6f);
    for (int i = tid; i < HH; i += 256)
        y[i] = (x[i] - mean) * inv * g[i] + b[i];
}

// ======================= bf16x3 MMA GEMM: C = A(MxK) @ B(KxN) =======================
// flags: 1 = bias, 2 = residual, 4 = relu. Block 128x128, K-tile 32. 256 thr (8 warps 2x4).
__global__ void gemm_mma(const float* __restrict__ A, const float* __restrict__ Bm,
                         const float* __restrict__ bias, const float* __restrict__ res,
                         float* __restrict__ C, int M, int N, int K, int flags) {
    __shared__ __nv_bfloat16 Ah[128][SPAD], Al[128][SPAD];
    __shared__ __nv_bfloat16 Bh[128][SPAD], Bl[128][SPAD];
    int tid = threadIdx.x;
    int wid = tid >> 5, lane = tid & 31;
    int wm = (wid >> 2) * 64;     // warp row base
    int wn = (wid & 3) * 32;      // warp col base
    int m0 = blockIdx.y * 128, n0 = blockIdx.x * 128;
    float acc[4][4][4] = {};

    for (int k0 = 0; k0 < K; k0 += 32) {
        // load A tile [128 rows][32 k]
        #pragma unroll
        for (int it = 0; it < 4; it++) {
            int r = (tid >> 3) + it * 32;
            int c = (tid & 7) * 4;
            float4 v = *(const float4*)&A[(size_t)(m0 + r) * K + k0 + c];
            split_store2(v.x, v.y, &Ah[r][c], &Al[r][c]);
            split_store2(v.z, v.w, &Ah[r][c + 2], &Al[r][c + 2]);
        }
        // load B tile [32 k][128 n] -> smem [n][k]
        #pragma unroll
        for (int it = 0; it < 4; it++) {
            int r = (tid >> 5) + it * 8;   // k row
            int c = (tid & 31) * 4;        // n col
            float4 v = *(const float4*)&Bm[(size_t)(k0 + r) * N + n0 + c];
            __nv_bfloat16 h0, l0;
            split1(v.x, h0, l0); Bh[c + 0][r] = h0; Bl[c + 0][r] = l0;
            split1(v.y, h0, l0); Bh[c + 1][r] = h0; Bl[c + 1][r] = l0;
            split1(v.z, h0, l0); Bh[c + 2][r] = h0; Bl[c + 2][r] = l0;
            split1(v.w, h0, l0); Bh[c + 3][r] = h0; Bl[c + 3][r] = l0;
        }
        __syncthreads();
        #pragma unroll
        for (int ks = 0; ks < 32; ks += 16) {
            int kb = ks + (lane & 3) * 2;
            unsigned ah[4][4], al[4][4], bh[4][2], bl[4][2];
            #pragma unroll
            for (int mt = 0; mt < 4; mt++) {
                int r0 = wm + mt * 16 + (lane >> 2);
                ah[mt][0] = U32AT(Ah[r0][kb]);     ah[mt][1] = U32AT(Ah[r0 + 8][kb]);
                ah[mt][2] = U32AT(Ah[r0][kb + 8]); ah[mt][3] = U32AT(Ah[r0 + 8][kb + 8]);
                al[mt][0] = U32AT(Al[r0][kb]);     al[mt][1] = U32AT(Al[r0 + 8][kb]);
                al[mt][2] = U32AT(Al[r0][kb + 8]); al[mt][3] = U32AT(Al[r0 + 8][kb + 8]);
            }
            #pragma unroll
            for (int nt = 0; nt < 4; nt++) {
                int c0 = wn + nt * 8 + (lane >> 2);
                bh[nt][0] = U32AT(Bh[c0][kb]); bh[nt][1] = U32AT(Bh[c0][kb + 8]);
                bl[nt][0] = U32AT(Bl[c0][kb]); bl[nt][1] = U32AT(Bl[c0][kb + 8]);
            }
            #pragma unroll
            for (int mt = 0; mt < 4; mt++)
                #pragma unroll
                for (int nt = 0; nt < 4; nt++) {
                    mma16816(acc[mt][nt], ah[mt], bh[nt]);
                    mma16816(acc[mt][nt], ah[mt], bl[nt]);
                    mma16816(acc[mt][nt], al[mt], bh[nt]);
                }
        }
        __syncthreads();
    }
    // epilogue
    #pragma unroll
    for (int mt = 0; mt < 4; mt++) {
        #pragma unroll
        for (int nt = 0; nt < 4; nt++) {
            #pragma unroll
            for (int i = 0; i < 4; i++) {
                int row = m0 + wm + mt * 16 + (lane >> 2) + ((i >> 1) ? 8 : 0);
                int col = n0 + wn + nt * 8 + (lane & 3) * 2 + (i & 1);
                float v = acc[mt][nt][i];
                if (flags & 1) v += bias[col];
                if (flags & 2) v += res[(size_t)row * N + col];
                if (flags & 4) v = fmaxf(v, 0.f);
                C[(size_t)row * N + col] = v;
            }
        }
    }
}

// ======================= attention scores (bf16x3 MMA) =======================
// S[bh,t,s] = (q . k)/8, masked. Block 128(t) x 128(s), K = 64.
__global__ void scores_mma(const float* __restrict__ Q, const float* __restrict__ Km,
                           float* __restrict__ Sout, const unsigned char* __restrict__ pad,
                           int Tq, int Tk, int causal) {
    __shared__ __nv_bfloat16 Ah[128][SPAD], Al[128][SPAD];
    __shared__ __nv_bfloat16 Bh[128][SPAD], Bl[128][SPAD];
    int tid = threadIdx.x;
    int wid = tid >> 5, lane = tid & 31;
    int wm = (wid >> 2) * 64, wn = (wid & 3) * 32;
    int bh = blockIdx.z, b = bh / NHH, h = bh % NHH;
    int t0 = blockIdx.y * 128, s0 = blockIdx.x * 128;
    const float* Qb = Q + ((size_t)(b * Tq + t0)) * HH + h * DHD;
    const float* Kb = Km + ((size_t)(b * Tk + s0)) * HH + h * DHD;
    float acc[4][4][4] = {};

    for (int k0 = 0; k0 < 64; k0 += 32) {
        #pragma unroll
        for (int it = 0; it < 4; it++) {
            int r = (tid >> 3) + it * 32;
            int c = (tid & 7) * 4;
            float4 v = *(const float4*)&Qb[(size_t)r * HH + k0 + c];
            split_store2(v.x, v.y, &Ah[r][c], &Al[r][c]);
            split_store2(v.z, v.w, &Ah[r][c + 2], &Al[r][c + 2]);
            float4 u = *(const float4*)&Kb[(size_t)r * HH + k0 + c];
            split_store2(u.x, u.y, &Bh[r][c], &Bl[r][c]);
            split_store2(u.z, u.w, &Bh[r][c + 2], &Bl[r][c + 2]);
        }
        __syncthreads();
        #pragma unroll
        for (int ks = 0; ks < 32; ks += 16) {
            int kb = ks + (lane & 3) * 2;
            unsigned ah[4][4], al[4][4], bh[4][2], bl[4][2];
            #pragma unroll
            for (int mt = 0; mt < 4; mt++) {
                int r0 = wm + mt * 16 + (lane >> 2);
                ah[mt][0] = U32AT(Ah[r0][kb]);     ah[mt][1] = U32AT(Ah[r0 + 8][kb]);
                ah[mt][2] = U32AT(Ah[r0][kb + 8]); ah[mt][3] = U32AT(Ah[r0 + 8][kb + 8]);
                al[mt][0] = U32AT(Al[r0][kb]);     al[mt][1] = U32AT(Al[r0 + 8][kb]);
                al[mt][2] = U32AT(Al[r0][kb + 8]); al[mt][3] = U32AT(Al[r0 + 8][kb + 8]);
            }
            #pragma unroll
            for (int nt = 0; nt < 4; nt++) {
                int c0 = wn + nt * 8 + (lane >> 2);
                bh[nt][0] = U32AT(Bh[c0][kb]); bh[nt][1] = U32AT(Bh[c0][kb + 8]);
                bl[nt][0] = U32AT(Bl[c0][kb]); bl[nt][1] = U32AT(Bl[c0][kb + 8]);
            }
            #pragma unroll
            for (int mt = 0; mt < 4; mt++)
                #pragma unroll
                for (int nt = 0; nt < 4; nt++) {
                    mma16816(acc[mt][nt], ah[mt], bh[nt]);
                    mma16816(acc[mt][nt], ah[mt], bl[nt]);
                    mma16816(acc[mt][nt], al[mt], bh[nt]);
                }
        }
        __syncthreads();
    }
    #pragma unroll
    for (int mt = 0; mt < 4; mt++)
        #pragma unroll
        for (int nt = 0; nt < 4; nt++)
            #pragma unroll
            for (int i = 0; i < 4; i++) {
                int t = t0 + wm + mt * 16 + (lane >> 2) + ((i >> 1) ? 8 : 0);
                int s = s0 + wn + nt * 8 + (lane & 3) * 2 + (i & 1);
                float v = acc[mt][nt][i] * 0.125f;
                bool m = (causal && (s > t)) || (pad[(size_t)b * Tk + s] != 0);
                Sout[((size_t)bh * Tq + t) * Tk + s] = m ? -1e18f : v;
            }
}

// ======================= ctx (bf16x3 MMA): C = W @ V =======================
// Block 128(t) x 64(d). 8 warps (4x2), warp 32x32.
__global__ void ctx_mma(const float* __restrict__ W, const float* __restrict__ Vm,
                        float* __restrict__ C, int Tq, int Tk) {
    __shared__ __nv_bfloat16 Ah[128][SPAD], Al[128][SPAD];
    __shared__ __nv_bfloat16 Bh[64][SPAD], Bl[64][SPAD];
    int tid = threadIdx.x;
    int wid = tid >> 5, lane = tid & 31;
    int wm = (wid >> 1) * 32, wn = (wid & 1) * 32;
    int bh = blockIdx.z, b = bh / NHH, h = bh % NHH;
    int t0 = blockIdx.y * 128;
    const float* Wb = W + ((size_t)bh * Tq + t0) * Tk;
    const float* Vb = Vm + ((size_t)b * Tk) * HH + h * DHD;
    float acc[2][4][4] = {};

    for (int k0 = 0; k0 < Tk; k0 += 32) {
        #pragma unroll
        for (int it = 0; it < 4; it++) {
            int r = (tid >> 3) + it * 32;
            int c = (tid & 7) * 4;
            float4 v = *(const float4*)&Wb[(size_t)r * Tk + k0 + c];
            split_store2(v.x, v.y, &Ah[r][c], &Al[r][c]);
            split_store2(v.z, v.w, &Ah[r][c + 2], &Al[r][c + 2]);
        }
        // V tile [32 s][64 d] -> smem [d][s]
        #pragma unroll
        for (int it = 0; it < 2; it++) {
            int r = (tid >> 4) + it * 16;   // s row
            int c = (tid & 15) * 4;         // d col
            float4 v = *(const float4*)&Vb[(size_t)(k0 + r) * HH + c];
            __nv_bfloat16 h0, l0;
            split1(v.x, h0, l0); Bh[c + 0][r] = h0; Bl[c + 0][r] = l0;
            split1(v.y, h0, l0); Bh[c + 1][r] = h0; Bl[c + 1][r] = l0;
            split1(v.z, h0, l0); Bh[c + 2][r] = h0; Bl[c + 2][r] = l0;
            split1(v.w, h0, l0); Bh[c + 3][r] = h0; Bl[c + 3][r] = l0;
        }
        __syncthreads();
        #pragma unroll
        for (int ks = 0; ks < 32; ks += 16) {
            int kb = ks + (lane & 3) * 2;
            unsigned ah[2][4], al[2][4], bh[4][2], bl[4][2];
            #pragma unroll
            for (int mt = 0; mt < 2; mt++) {
                int r0 = wm + mt * 16 + (lane >> 2);
                ah[mt][0] = U32AT(Ah[r0][kb]);     ah[mt][1] = U32AT(Ah[r0 + 8][kb]);
                ah[mt][2] = U32AT(Ah[r0][kb + 8]); ah[mt][3] = U32AT(Ah[r0 + 8][kb + 8]);
                al[mt][0] = U32AT(Al[r0][kb]);     al[mt][1] = U32AT(Al[r0 + 8][kb]);
                al[mt][2] = U32AT(Al[r0][kb + 8]); al[mt][3] = U32AT(Al[r0 + 8][kb + 8]);
            }
            #pragma unroll
            for (int nt = 0; nt < 4; nt++) {
                int c0 = wn + nt * 8 + (lane >> 2);
                bh[nt][0] = U32AT(Bh[c0][kb]); bh[nt][1] = U32AT(Bh[c0][kb + 8]);
                bl[nt][0] = U32AT(Bl[c0][kb]); bl[nt][1] = U32AT(Bl[c0][kb + 8]);
            }
            #pragma unroll
            for (int mt = 0; mt < 2; mt++)
                #pragma unroll
                for (int nt = 0; nt < 4; nt++) {
                    mma16816(acc[mt][nt], ah[mt], bh[nt]);
                    mma16816(acc[mt][nt], ah[mt], bl[nt]);
                    mma16816(acc[mt][nt], al[mt], bh[nt]);
                }
        }
        __syncthreads();
    }
    #pragma unroll
    for (int mt = 0; mt < 2; mt++)
        #pragma unroll
        for (int nt = 0; nt < 4; nt++)
            #pragma unroll
            for (int i = 0; i < 4; i++) {
                int t = t0 + wm + mt * 16 + (lane >> 2) + ((i >> 1) ? 8 : 0);
                int d = wn + nt * 8 + (lane & 3) * 2 + (i & 1);
                C[((size_t)(b * Tq) + t) * HH + h * DHD + d] = acc[mt][nt][i];
            }
}

// ---------------- softmax over last dim, in place ----------------
__global__ void softmax_kernel(float* __restrict__ Sc, int Tk) {
    __shared__ float red[256];
    long row = blockIdx.x;
    float* p = Sc + row * Tk;
    int tid = threadIdx.x;
    float mx = -3.0e38f;
    for (int i = tid; i < Tk; i += 256) mx = fmaxf(mx, p[i]);
    red[tid] = mx; __syncthreads();
    for (int s = 128; s > 0; s >>= 1) {
        if (tid < s) red[tid] = fmaxf(red[tid], red[tid + s]);
        __syncthreads();
    }
    mx = red[0]; __syncthreads();
    float sum = 0.f;
    for (int i = tid; i < Tk; i += 256) {
        float e = expf(p[i] - mx);
        p[i] = e;
        sum += e;
    }
    float tot = block_reduce_sum(sum, red);
    float inv = 1.0f / tot;
    for (int i = tid; i < Tk; i += 256) p[i] *= inv;
}

// ---------------- save residual stream into result2 (B,L,T,H) ----------------
__global__ void save_kernel(float* __restrict__ out_r2, int l) {
    long idx = (long)blockIdx.x * blockDim.x + threadIdx.x;
    int h = (int)(idx % HH);
    long bt = idx / HH;
    int t = (int)(bt % TT);
    int b = (int)(bt / TT);
    out_r2[(((long)b * LL + l) * TT + t) * HH + h] = g_x[idx];
}

// ---------------- avg attention weights over heads (last cross layer) ----------------
__global__ void aw_kernel(float* __restrict__ out_ws) {
    long idx = (long)blockIdx.x * blockDim.x + threadIdx.x;
    int s = (int)(idx % SS);
    long bt = idx / SS;
    int t = (int)(bt % TT);
    int b = (int)(bt / TT);
    float acc = 0.f;
    #pragma unroll
    for (int h = 0; h < NHH; h++)
        acc += g_scores[(((long)(b * NHH + h)) * TT + t) * SS + s];
    out_ws[idx] = acc * (1.0f / NHH);
}

// ---------------- p_trans head ----------------
__global__ void wt_kernel(const float* __restrict__ Wt1, const float* __restrict__ Wt2) {
    __shared__ float red[256];
    int i = blockIdx.x;
    float s = 0.f;
    for (int j = threadIdx.x; j < HH; j += 256)
        s += Wt1[(long)i * HH + j] * Wt2[j];
    float tot = block_reduce_sum(s, red);
    if (threadIdx.x == 0) g_wt[i] = tot;
}

__global__ void p_kernel(const float* __restrict__ X, float* __restrict__ outp) {
    __shared__ float red[256];
    long row = blockIdx.x;
    const float* xr = X + row * HH;
    float s = 0.f;
    for (int i = threadIdx.x; i < HH; i += 256) s += xr[i] * g_wt[i];
    float tot = block_reduce_sum(s, red);
    if (threadIdx.x == 0) outp[row] = 1.0f / (1.0f + expf(-tot));
}

// ---------------- driver ----------------
extern "C" void kernel_launch(void* const* d_in, const int* in_sizes, int n_in,
                              void* d_out, int out_size) {
    const int*            tgt      = (const int*)d_in[0];
    const unsigned char*  src_pad  = (const unsigned char*)d_in[1];
    const unsigned char*  tgt_pad  = (const unsigned char*)d_in[2];
    const float*          enc_out  = (const float*)d_in[3];
    const float*          emb      = (const float*)d_in[4];
    const float*          Wq_self  = (const float*)d_in[5];
    const float*          Wk_self  = (const float*)d_in[6];
    const float*          Wv_self  = (const float*)d_in[7];
    const float*          Wo_self  = (const float*)d_in[8];
    const float*          bo_self  = (const float*)d_in[9];
    const float*          Wq_src   = (const float*)d_in[10];
    const float*          Wk_src   = (const float*)d_in[11];
    const float*          Wv_src   = (const float*)d_in[12];
    const float*          Wo_src   = (const float*)d_in[13];
    const float*          bo_src   = (const float*)d_in[14];
    const float*          W1       = (const float*)d_in[15];
    const float*          W2       = (const float*)d_in[16];
    const float*          ln_g     = (const float*)d_in[17];
    const float*          ln_b     = (const float*)d_in[18];
    const float*          final_g  = (const float*)d_in[19];
    const float*          final_b  = (const float*)d_in[20];
    const float*          Wt1      = (const float*)d_in[21];
    const float*          Wt2      = (const float*)d_in[22];

    float* out    = (float*)d_out;
    float* out_r1 = out;                                    // (B,T,H)
    float* out_r2 = out + (size_t)BB * TT * HH;             // (B,L,T,H)
    float* out_p  = out_r2 + (size_t)BB * LL * TT * HH;     // (B,T,1)
    float* out_ws = out_p + (size_t)BB * TT;                // (B,T,S)

    float *x, *h, *q, *k, *v, *ctx, *sc, *ffn;
    cudaGetSymbolAddress((void**)&x,   g_x);
    cudaGetSymbolAddress((void**)&h,   g_h);
    cudaGetSymbolAddress((void**)&q,   g_q);
    cudaGetSymbolAddress((void**)&k,   g_k);
    cudaGetSymbolAddress((void**)&v,   g_v);
    cudaGetSymbolAddress((void**)&ctx, g_ctx);
    cudaGetSymbolAddress((void**)&sc,  g_scores);
    cudaGetSymbolAddress((void**)&ffn, g_ffn);

    const int MT = BB * TT;   // 2048
    const int MS = BB * SS;   // 4096

    invfreq_kernel<<<4, 256>>>();
    pe_kernel<<<TT * HH / 256, 256>>>();
    embed_kernel<<<BB * TT * HH / 256, 256>>>(tgt, emb);
    wt_kernel<<<HH, 256>>>(Wt1, Wt2);

    for (int l = 0; l < LL; l++) {
        save_kernel<<<BB * TT * HH / 256, 256>>>(out_r2, l);

        // --- self attention ---
        ln_kernel<<<MT, 256>>>(x, ln_g + (size_t)(l * 3 + 0) * HH, ln_b + (size_t)(l * 3 + 0) * HH, h);
        gemm_mma<<<dim3(HH / 128, MT / 128), 256>>>(h, Wq_self + (size_t)l * HH * HH, nullptr, nullptr, q, MT, HH, HH, 0);
        gemm_mma<<<dim3(HH / 128, MT / 128), 256>>>(h, Wk_self + (size_t)l * HH * HH, nullptr, nullptr, k, MT, HH, HH, 0);
        gemm_mma<<<dim3(HH / 128, MT / 128), 256>>>(h, Wv_self + (size_t)l * HH * HH, nullptr, nullptr, v, MT, HH, HH, 0);
        scores_mma<<<dim3(TT / 128, TT / 128, BB * NHH), 256>>>(q, k, sc, tgt_pad, TT, TT, 1);
        softmax_kernel<<<BB * NHH * TT, 256>>>(sc, TT);
        ctx_mma<<<dim3(1, TT / 128, BB * NHH), 256>>>(sc, v, ctx, TT, TT);
        gemm_mma<<<dim3(HH / 128, MT / 128), 256>>>(ctx, Wo_self + (size_t)l * HH * HH, bo_self + (size_t)l * HH, x, x, MT, HH, HH, 3);

        // --- cross attention ---
        ln_kernel<<<MT, 256>>>(x, ln_g + (size_t)(l * 3 + 1) * HH, ln_b + (size_t)(l * 3 + 1) * HH, h);
        gemm_mma<<<dim3(HH / 128, MT / 128), 256>>>(h, Wq_src + (size_t)l * HH * HH, nullptr, nullptr, q, MT, HH, HH, 0);
        gemm_mma<<<dim3(HH / 128, MS / 128), 256>>>(enc_out, Wk_src + (size_t)l * HH * HH, nullptr, nullptr, k, MS, HH, HH, 0);
        gemm_mma<<<dim3(HH / 128, MS / 128), 256>>>(enc_out, Wv_src + (size_t)l * HH * HH, nullptr, nullptr, v, MS, HH, HH, 0);
        scores_mma<<<dim3(SS / 128, TT / 128, BB * NHH), 256>>>(q, k, sc, src_pad, TT, SS, 0);
        softmax_kernel<<<BB * NHH * TT, 256>>>(sc, SS);
        if (l == LL - 1)
            aw_kernel<<<BB * TT * SS / 256, 256>>>(out_ws);
        ctx_mma<<<dim3(1, TT / 128, BB * NHH), 256>>>(sc, v, ctx, TT, SS);
        gemm_mma<<<dim3(HH / 128, MT / 128), 256>>>(ctx, Wo_src + (size_t)l * HH * HH, bo_src + (size_t)l * HH, x, x, MT, HH, HH, 3);

        // --- feed forward ---
        ln_kernel<<<MT, 256>>>(x, ln_g + (size_t)(l * 3 + 2) * HH, ln_b + (size_t)(l * 3 + 2) * HH, h);
        gemm_mma<<<dim3(FF / 128, MT / 128), 256>>>(h, W1 + (size_t)l * HH * FF, nullptr, nullptr, ffn, MT, FF, HH, 4);
        gemm_mma<<<dim3(HH / 128, MT / 128), 256>>>(ffn, W2 + (size_t)l * FF * HH, nullptr, x, x, MT, HH, FF, 2);
    }

    ln_kernel<<<MT, 256>>>(x, final_g, final_b, out_r1);
    p_kernel<<<MT, 256>>>(x, out_p);
}

// round 3
// speedup vs baseline: 3.1799x; 1.4355x over previous
#include <cuda_runtime.h>
#include <cuda_bf16.h>
#include <math.h>

#define BB 4
#define TT 512
#define SS 1024
#define HH 1024
#define FF 4096
#define NHH 16
#define DHD 64
#define LL 6

// weight split buffer offsets (elements)
#define OFF_WQS 0
#define OFF_WKS 6291456
#define OFF_WVS 12582912
#define OFF_WOS 18874368
#define OFF_WQX 25165824
#define OFF_WKX 31457280
#define OFF_WVX 37748736
#define OFF_WOX 44040192
#define OFF_W1  50331648
#define OFF_W2  75497472
#define WTOT    100663296

// ---------------- device global scratch ----------------
__device__ __nv_bfloat16 g_wbh[WTOT], g_wbl[WTOT];          // split weights
__device__ __nv_bfloat16 g_eh[BB*SS*HH], g_el[BB*SS*HH];    // split enc_out
__device__ __nv_bfloat16 g_hh[BB*TT*HH], g_hl[BB*TT*HH];    // ln out
__device__ __nv_bfloat16 g_qh[BB*TT*HH], g_ql[BB*TT*HH];
__device__ __nv_bfloat16 g_kh[BB*SS*HH], g_kl[BB*SS*HH];
__device__ __nv_bfloat16 g_vh[BB*SS*HH], g_vl[BB*SS*HH];
__device__ __nv_bfloat16 g_ch[BB*TT*HH], g_cl[BB*TT*HH];    // ctx out
__device__ __nv_bfloat16 g_fh[BB*TT*FF], g_fl[BB*TT*FF];    // ffn mid
__device__ __nv_bfloat16 g_sch[(size_t)BB*NHH*TT*SS], g_scl[(size_t)BB*NHH*TT*SS];
__device__ float g_x[BB*TT*HH];
__device__ float g_scores[(size_t)BB*NHH*TT*SS];
__device__ float g_pe[TT*HH];
__device__ double g_invf[HH];
__device__ float g_wt[HH];

// ---------------- helpers ----------------
__device__ __forceinline__ float block_reduce_sum(float v, float* red) {
    int tid = threadIdx.x;
    red[tid] = v; __syncthreads();
    for (int s = 128; s > 0; s >>= 1) {
        if (tid < s) red[tid] += red[tid + s];
        __syncthreads();
    }
    float r = red[0]; __syncthreads();
    return r;
}

__device__ __forceinline__ void mma16816(float c[4], const unsigned a[4], const unsigned b[2]) {
    asm volatile("mma.sync.aligned.m16n8k16.row.col.f32.bf16.bf16.f32 "
        "{%0,%1,%2,%3}, {%4,%5,%6,%7}, {%8,%9}, {%0,%1,%2,%3};"
        : "+f"(c[0]), "+f"(c[1]), "+f"(c[2]), "+f"(c[3])
        : "r"(a[0]), "r"(a[1]), "r"(a[2]), "r"(a[3]), "r"(b[0]), "r"(b[1]));
}

__device__ __forceinline__ void ldsm4(unsigned& r0, unsigned& r1, unsigned& r2, unsigned& r3,
                                      const void* p) {
    unsigned a = (unsigned)__cvta_generic_to_shared(p);
    asm volatile("ldmatrix.sync.aligned.m8n8.x4.shared.b16 {%0,%1,%2,%3}, [%4];"
        : "=r"(r0), "=r"(r1), "=r"(r2), "=r"(r3) : "r"(a));
}
__device__ __forceinline__ void ldsm4t(unsigned& r0, unsigned& r1, unsigned& r2, unsigned& r3,
                                       const void* p) {
    unsigned a = (unsigned)__cvta_generic_to_shared(p);
    asm volatile("ldmatrix.sync.aligned.m8n8.x4.trans.shared.b16 {%0,%1,%2,%3}, [%4];"
        : "=r"(r0), "=r"(r1), "=r"(r2), "=r"(r3) : "r"(a));
}

__device__ __forceinline__ void cpa16(void* dst, const void* src) {
    unsigned d = (unsigned)__cvta_generic_to_shared(dst);
    asm volatile("cp.async.ca.shared.global [%0], [%1], 16;" :: "r"(d), "l"(src));
}
#define CP_COMMIT asm volatile("cp.async.commit_group;")
#define CP_WAIT0 asm volatile("cp.async.wait_group 0;")
#define CP_WAIT1 asm volatile("cp.async.wait_group 1;")

__device__ __forceinline__ void split_w2(float v0, float v1, __nv_bfloat16* hp, __nv_bfloat16* lp) {
    __nv_bfloat16 h0 = __float2bfloat16(v0), h1 = __float2bfloat16(v1);
    *(__nv_bfloat162*)hp = __halves2bfloat162(h0, h1);
    *(__nv_bfloat162*)lp = __halves2bfloat162(__float2bfloat16(v0 - __bfloat162float(h0)),
                                              __float2bfloat16(v1 - __bfloat162float(h1)));
}

// ---------------- split conversion ----------------
__global__ void split_kernel(const float* __restrict__ src, __nv_bfloat16* __restrict__ h,
                             __nv_bfloat16* __restrict__ l, long n) {
    long i = ((long)blockIdx.x * blockDim.x + threadIdx.x) * 4;
    if (i < n) {
        float4 v = *(const float4*)(src + i);
        split_w2(v.x, v.y, h + i, l + i);
        split_w2(v.z, v.w, h + i + 2, l + i + 2);
    }
}

// ---------------- embedding / positional ----------------
__global__ void invfreq_kernel() {
    int h = blockIdx.x * blockDim.x + threadIdx.x;
    if (h < HH) {
        double e = (double)(2 * (h / 2)) / (double)HH;
        g_invf[h] = pow(10000.0, -e);
    }
}
__global__ void pe_kernel() {
    int idx = blockIdx.x * blockDim.x + threadIdx.x;
    int t = idx / HH, h = idx % HH;
    double ang = (double)t * g_invf[h];
    g_pe[idx] = (float)((h & 1) ? cos(ang) : sin(ang));
}
__global__ void embed_kernel(const int* __restrict__ tgt, const float* __restrict__ emb) {
    long idx = (long)blockIdx.x * blockDim.x + threadIdx.x;
    int h = (int)(idx % HH);
    long bt = idx / HH;
    int tok = tgt[bt];
    int t = (int)(bt % TT);
    g_x[idx] = emb[(long)tok * HH + h] * 32.0f + g_pe[t * HH + h];
}

// ---------------- layernorm: fp32 out OR split bf16 out ----------------
__global__ void ln_kernel(const float* __restrict__ X, const float* __restrict__ g,
                          const float* __restrict__ b, float* __restrict__ Yf,
                          __nv_bfloat16* __restrict__ Yh, __nv_bfloat16* __restrict__ Yl) {
    __shared__ float red[256];
    long row = blockIdx.x;
    const float* x = X + row * HH;
    int tid = threadIdx.x;
    float s = 0.f;
    for (int i = tid; i < HH; i += 256) s += x[i];
    float mean = block_reduce_sum(s, red) * (1.0f / HH);
    float v = 0.f;
    for (int i = tid; i < HH; i += 256) { float d = x[i] - mean; v += d * d; }
    float var = block_reduce_sum(v, red) * (1.0f / HH);
    float inv = 1.0f / sqrtf(var + 1e-6f);
    if (Yf) {
        for (int i = tid; i < HH; i += 256)
            Yf[row * HH + i] = (x[i] - mean) * inv * g[i] + b[i];
    } else {
        for (int i = tid * 2; i < HH; i += 512) {
            float y0 = (x[i] - mean) * inv * g[i] + b[i];
            float y1 = (x[i + 1] - mean) * inv * g[i + 1] + b[i + 1];
            split_w2(y0, y1, Yh + row * HH + i, Yl + row * HH + i);
        }
    }
}

// ======================= pipelined bf16x3 GEMM =======================
// C = A(MxK)@B(KxN). flags: 1 bias, 2 residual, 4 relu, 8 split-out
#define APITCH 40
#define BPITCH 136
__global__ void __launch_bounds__(256) gemm_bf(
    const __nv_bfloat16* __restrict__ Ah, const __nv_bfloat16* __restrict__ Al,
    const __nv_bfloat16* __restrict__ Bh, const __nv_bfloat16* __restrict__ Bl,
    const float* __restrict__ bias, const float* __restrict__ res,
    float* __restrict__ Cf, __nv_bfloat16* __restrict__ Ch, __nv_bfloat16* __restrict__ Cl,
    int M, int N, int K, int flags) {
    extern __shared__ __nv_bfloat16 sm[];
    __nv_bfloat16* sAh = sm;                      // [2][128][APITCH]
    __nv_bfloat16* sAl = sAh + 2 * 128 * APITCH;
    __nv_bfloat16* sBh = sAl + 2 * 128 * APITCH;  // [2][32][BPITCH]
    __nv_bfloat16* sBl = sBh + 2 * 32 * BPITCH;
    int tid = threadIdx.x, lane = tid & 31, wid = tid >> 5;
    int wm = (wid >> 2) * 64, wn = (wid & 3) * 32;
    int m0 = blockIdx.y * 128, n0 = blockIdx.x * 128;
    float acc[4][4][4] = {};

    // prologue loads
    {
        #pragma unroll
        for (int i = 0; i < 2; i++) {
            int idx = tid + i * 256;
            int r = idx >> 2, c = (idx & 3) * 8;
            cpa16(sAh + r * APITCH + c, Ah + (size_t)(m0 + r) * K + c);
            cpa16(sAl + r * APITCH + c, Al + (size_t)(m0 + r) * K + c);
        }
        #pragma unroll
        for (int i = 0; i < 2; i++) {
            int idx = tid + i * 256;
            int r = idx >> 4, c = (idx & 15) * 8;
            cpa16(sBh + r * BPITCH + c, Bh + (size_t)r * N + n0 + c);
            cpa16(sBl + r * BPITCH + c, Bl + (size_t)r * N + n0 + c);
        }
        CP_COMMIT;
    }
    int ntiles = K / 32;
    for (int t = 0; t < ntiles; t++) {
        if (t + 1 < ntiles) {
            int st = (t + 1) & 1, k0 = (t + 1) * 32;
            #pragma unroll
            for (int i = 0; i < 2; i++) {
                int idx = tid + i * 256;
                int r = idx >> 2, c = (idx & 3) * 8;
                cpa16(sAh + st * 128 * APITCH + r * APITCH + c, Ah + (size_t)(m0 + r) * K + k0 + c);
                cpa16(sAl + st * 128 * APITCH + r * APITCH + c, Al + (size_t)(m0 + r) * K + k0 + c);
            }
            #pragma unroll
            for (int i = 0; i < 2; i++) {
                int idx = tid + i * 256;
                int r = idx >> 4, c = (idx & 15) * 8;
                cpa16(sBh + st * 32 * BPITCH + r * BPITCH + c, Bh + (size_t)(k0 + r) * N + n0 + c);
                cpa16(sBl + st * 32 * BPITCH + r * BPITCH + c, Bl + (size_t)(k0 + r) * N + n0 + c);
            }
            CP_COMMIT;
            CP_WAIT1;
        } else {
            CP_WAIT0;
        }
        __syncthreads();
        int st = t & 1;
        __nv_bfloat16* cAh = sAh + st * 128 * APITCH;
        __nv_bfloat16* cAl = sAl + st * 128 * APITCH;
        __nv_bfloat16* cBh = sBh + st * 32 * BPITCH;
        __nv_bfloat16* cBl = sBl + st * 32 * BPITCH;
        #pragma unroll
        for (int ks = 0; ks < 32; ks += 16) {
            unsigned bh[4][2], bl[4][2];
            #pragma unroll
            for (int np = 0; np < 2; np++) {
                int r = ks + (lane & 7) + ((lane >> 3) & 1) * 8;
                int c = wn + np * 16 + (lane >> 4) * 8;
                ldsm4t(bh[np*2][0], bh[np*2][1], bh[np*2+1][0], bh[np*2+1][1], cBh + r * BPITCH + c);
                ldsm4t(bl[np*2][0], bl[np*2][1], bl[np*2+1][0], bl[np*2+1][1], cBl + r * BPITCH + c);
            }
            #pragma unroll
            for (int mt = 0; mt < 4; mt++) {
                int r = wm + mt * 16 + (lane & 7) + ((lane >> 3) & 1) * 8;
                int c = ks + (lane >> 4) * 8;
                unsigned ah[4], al[4];
                ldsm4(ah[0], ah[1], ah[2], ah[3], cAh + r * APITCH + c);
                ldsm4(al[0], al[1], al[2], al[3], cAl + r * APITCH + c);
                #pragma unroll
                for (int nt = 0; nt < 4; nt++) {
                    mma16816(acc[mt][nt], ah, bh[nt]);
                    mma16816(acc[mt][nt], al, bh[nt]);
                    mma16816(acc[mt][nt], ah, bl[nt]);
                }
            }
        }
        __syncthreads();
    }
    #pragma unroll
    for (int mt = 0; mt < 4; mt++)
        #pragma unroll
        for (int nt = 0; nt < 4; nt++)
            #pragma unroll
            for (int half = 0; half < 2; half++) {
                int row = m0 + wm + mt * 16 + (lane >> 2) + half * 8;
                int col = n0 + wn + nt * 8 + (lane & 3) * 2;
                float v0 = acc[mt][nt][half * 2], v1 = acc[mt][nt][half * 2 + 1];
                if (flags & 1) { v0 += bias[col]; v1 += bias[col + 1]; }
                if (flags & 2) { float2 rr = *(const float2*)&res[(size_t)row * N + col]; v0 += rr.x; v1 += rr.y; }
                if (flags & 4) { v0 = fmaxf(v0, 0.f); v1 = fmaxf(v1, 0.f); }
                if (flags & 8) split_w2(v0, v1, Ch + (size_t)row * N + col, Cl + (size_t)row * N + col);
                else *(float2*)&Cf[(size_t)row * N + col] = make_float2(v0, v1);
            }
}

// ======================= attention scores =======================
#define SPITCH 72
__global__ void __launch_bounds__(256) scores_bf(
    const __nv_bfloat16* __restrict__ Qh, const __nv_bfloat16* __restrict__ Ql,
    const __nv_bfloat16* __restrict__ Kh, const __nv_bfloat16* __restrict__ Kl,
    float* __restrict__ Sout, const unsigned char* __restrict__ pad,
    int Tq, int Tk, int causal) {
    extern __shared__ __nv_bfloat16 sm[];
    __nv_bfloat16* sQh = sm;                  // [128][SPITCH]
    __nv_bfloat16* sQl = sQh + 128 * SPITCH;
    __nv_bfloat16* sKh = sQl + 128 * SPITCH;
    __nv_bfloat16* sKl = sKh + 128 * SPITCH;
    int tid = threadIdx.x, lane = tid & 31, wid = tid >> 5;
    int wm = (wid >> 2) * 64, wn = (wid & 3) * 32;
    int bh = blockIdx.z, b = bh >> 4, h = bh & 15;
    int t0 = blockIdx.y * 128, s0 = blockIdx.x * 128;
    const __nv_bfloat16* Qbh = Qh + ((size_t)(b * Tq + t0)) * HH + h * DHD;
    const __nv_bfloat16* Qbl = Ql + ((size_t)(b * Tq + t0)) * HH + h * DHD;
    const __nv_bfloat16* Kbh = Kh + ((size_t)(b * Tk + s0)) * HH + h * DHD;
    const __nv_bfloat16* Kbl = Kl + ((size_t)(b * Tk + s0)) * HH + h * DHD;
    #pragma unroll
    for (int i = 0; i < 4; i++) {
        int idx = tid + i * 256;
        int r = idx >> 3, c = (idx & 7) * 8;
        cpa16(sQh + r * SPITCH + c, Qbh + (size_t)r * HH + c);
        cpa16(sQl + r * SPITCH + c, Qbl + (size_t)r * HH + c);
        cpa16(sKh + r * SPITCH + c, Kbh + (size_t)r * HH + c);
        cpa16(sKl + r * SPITCH + c, Kbl + (size_t)r * HH + c);
    }
    CP_COMMIT; CP_WAIT0;
    __syncthreads();
    float acc[4][4][4] = {};
    #pragma unroll
    for (int ks = 0; ks < 64; ks += 16) {
        unsigned bhf[4][2], blf[4][2];
        #pragma unroll
        for (int np = 0; np < 2; np++) {
            int r = wn + np * 16 + (lane & 7) + (lane >> 4) * 8;
            int c = ks + ((lane >> 3) & 1) * 8;
            ldsm4(bhf[np*2][0], bhf[np*2][1], bhf[np*2+1][0], bhf[np*2+1][1], sKh + r * SPITCH + c);
            ldsm4(blf[np*2][0], blf[np*2][1], blf[np*2+1][0], blf[np*2+1][1], sKl + r * SPITCH + c);
        }
        #pragma unroll
        for (int mt = 0; mt < 4; mt++) {
            int r = wm + mt * 16 + (lane & 7) + ((lane >> 3) & 1) * 8;
            int c = ks + (lane >> 4) * 8;
            unsigned ah[4], al[4];
            ldsm4(ah[0], ah[1], ah[2], ah[3], sQh + r * SPITCH + c);
            ldsm4(al[0], al[1], al[2], al[3], sQl + r * SPITCH + c);
            #pragma unroll
            for (int nt = 0; nt < 4; nt++) {
                mma16816(acc[mt][nt], ah, bhf[nt]);
                mma16816(acc[mt][nt], al, bhf[nt]);
                mma16816(acc[mt][nt], ah, blf[nt]);
            }
        }
    }
    #pragma unroll
    for (int mt = 0; mt < 4; mt++)
        #pragma unroll
        for (int nt = 0; nt < 4; nt++)
            #pragma unroll
            for (int i = 0; i < 4; i++) {
                int t = t0 + wm + mt * 16 + (lane >> 2) + ((i >> 1) ? 8 : 0);
                int s = s0 + wn + nt * 8 + (lane & 3) * 2 + (i & 1);
                float v = acc[mt][nt][i] * 0.125f;
                bool m = (causal && (s > t)) || (pad[(size_t)b * Tk + s] != 0);
                Sout[((size_t)bh * Tq + t) * Tk + s] = m ? -1e18f : v;
            }
}

// ======================= ctx = softmax @ V =======================
#define VPITCH 72
__global__ void __launch_bounds__(256) ctx_bf(
    const __nv_bfloat16* __restrict__ Wh, const __nv_bfloat16* __restrict__ Wl,
    const __nv_bfloat16* __restrict__ Vh, const __nv_bfloat16* __restrict__ Vl,
    __nv_bfloat16* __restrict__ Ch, __nv_bfloat16* __restrict__ Cl, int Tq, int Tk) {
    extern __shared__ __nv_bfloat16 sm[];
    __nv_bfloat16* sAh = sm;                      // [2][128][APITCH]
    __nv_bfloat16* sAl = sAh + 2 * 128 * APITCH;
    __nv_bfloat16* sBh = sAl + 2 * 128 * APITCH;  // [2][32][VPITCH]
    __nv_bfloat16* sBl = sBh + 2 * 32 * VPITCH;
    int tid = threadIdx.x, lane = tid & 31, wid = tid >> 5;
    int wm = (wid >> 1) * 32, wn = (wid & 1) * 32;
    int bh = blockIdx.z, b = bh >> 4, h = bh & 15;
    int t0 = blockIdx.y * 128;
    const __nv_bfloat16* Abh = Wh + ((size_t)bh * Tq + t0) * Tk;
    const __nv_bfloat16* Abl = Wl + ((size_t)bh * Tq + t0) * Tk;
    const __nv_bfloat16* Bbh = Vh + (size_t)b * Tk * HH + h * DHD;
    const __nv_bfloat16* Bbl = Vl + (size_t)b * Tk * HH + h * DHD;
    float acc[2][4][4] = {};
    {
        #pragma unroll
        for (int i = 0; i < 2; i++) {
            int idx = tid + i * 256;
            int r = idx >> 2, c = (idx & 3) * 8;
            cpa16(sAh + r * APITCH + c, Abh + (size_t)r * Tk + c);
            cpa16(sAl + r * APITCH + c, Abl + (size_t)r * Tk + c);
        }
        {
            int r = tid >> 3, c = (tid & 7) * 8;
            cpa16(sBh + r * VPITCH + c, Bbh + (size_t)r * HH + c);
            cpa16(sBl + r * VPITCH + c, Bbl + (size_t)r * HH + c);
        }
        CP_COMMIT;
    }
    int ntiles = Tk / 32;
    for (int t = 0; t < ntiles; t++) {
        if (t + 1 < ntiles) {
            int st = (t + 1) & 1, k0 = (t + 1) * 32;
            #pragma unroll
            for (int i = 0; i < 2; i++) {
                int idx = tid + i * 256;
                int r = idx >> 2, c = (idx & 3) * 8;
                cpa16(sAh + st * 128 * APITCH + r * APITCH + c, Abh + (size_t)r * Tk + k0 + c);
                cpa16(sAl + st * 128 * APITCH + r * APITCH + c, Abl + (size_t)r * Tk + k0 + c);
            }
            {
                int r = tid >> 3, c = (tid & 7) * 8;
                cpa16(sBh + st * 32 * VPITCH + r * VPITCH + c, Bbh + (size_t)(k0 + r) * HH + c);
                cpa16(sBl + st * 32 * VPITCH + r * VPITCH + c, Bbl + (size_t)(k0 + r) * HH + c);
            }
            CP_COMMIT;
            CP_WAIT1;
        } else {
            CP_WAIT0;
        }
        __syncthreads();
        int st = t & 1;
        __nv_bfloat16* cAh = sAh + st * 128 * APITCH;
        __nv_bfloat16* cAl = sAl + st * 128 * APITCH;
        __nv_bfloat16* cBh = sBh + st * 32 * VPITCH;
        __nv_bfloat16* cBl = sBl + st * 32 * VPITCH;
        #pragma unroll
        for (int ks = 0; ks < 32; ks += 16) {
            unsigned bhf[4][2], blf[4][2];
            #pragma unroll
            for (int np = 0; np < 2; np++) {
                int r = ks + (lane & 7) + ((lane >> 3) & 1) * 8;
                int c = wn + np * 16 + (lane >> 4) * 8;
                ldsm4t(bhf[np*2][0], bhf[np*2][1], bhf[np*2+1][0], bhf[np*2+1][1], cBh + r * VPITCH + c);
                ldsm4t(blf[np*2][0], blf[np*2][1], blf[np*2+1][0], blf[np*2+1][1], cBl + r * VPITCH + c);
            }
            #pragma unroll
            for (int mt = 0; mt < 2; mt++) {
                int r = wm + mt * 16 + (lane & 7) + ((lane >> 3) & 1) * 8;
                int c = ks + (lane >> 4) * 8;
                unsigned ah[4], al[4];
                ldsm4(ah[0], ah[1], ah[2], ah[3], cAh + r * APITCH + c);
                ldsm4(al[0], al[1], al[2], al[3], cAl + r * APITCH + c);
                #pragma unroll
                for (int nt = 0; nt < 4; nt++) {
                    mma16816(acc[mt][nt], ah, bhf[nt]);
                    mma16816(acc[mt][nt], al, bhf[nt]);
                    mma16816(acc[mt][nt], ah, blf[nt]);
                }
            }
        }
        __syncthreads();
    }
    #pragma unroll
    for (int mt = 0; mt < 2; mt++)
        #pragma unroll
        for (int nt = 0; nt < 4; nt++)
            #pragma unroll
            for (int half = 0; half < 2; half++) {
                int t = t0 + wm + mt * 16 + (lane >> 2) + half * 8;
                int d = wn + nt * 8 + (lane & 3) * 2;
                size_t o = ((size_t)(b * Tq) + t) * HH + h * DHD + d;
                split_w2(acc[mt][nt][half * 2], acc[mt][nt][half * 2 + 1], Ch + o, Cl + o);
            }
}

// ---------------- softmax: fp32 in -> split bf16 out ----------------
__global__ void softmax_kernel(const float* __restrict__ Sc, __nv_bfloat16* __restrict__ Oh,
                               __nv_bfloat16* __restrict__ Ol, int Tk) {
    __shared__ float red[256];
    long row = blockIdx.x;
    const float* p = Sc + row * Tk;
    int tid = threadIdx.x;
    float mx = -3.0e38f;
    for (int i = tid; i < Tk; i += 256) mx = fmaxf(mx, p[i]);
    red[tid] = mx; __syncthreads();
    for (int s = 128; s > 0; s >>= 1) {
        if (tid < s) red[tid] = fmaxf(red[tid], red[tid + s]);
        __syncthreads();
    }
    mx = red[0]; __syncthreads();
    float sum = 0.f;
    for (int i = tid; i < Tk; i += 256) sum += expf(p[i] - mx);
    float tot = block_reduce_sum(sum, red);
    float inv = 1.0f / tot;
    for (int i = tid * 2; i < Tk; i += 512) {
        float e0 = expf(p[i] - mx) * inv;
        float e1 = expf(p[i + 1] - mx) * inv;
        split_w2(e0, e1, Oh + row * Tk + i, Ol + row * Tk + i);
    }
}

// ---------------- misc ----------------
__global__ void save_kernel(float* __restrict__ out_r2, int l) {
    long idx = (long)blockIdx.x * blockDim.x + threadIdx.x;
    int h = (int)(idx % HH);
    long bt = idx / HH;
    int t = (int)(bt % TT);
    int b = (int)(bt / TT);
    out_r2[(((long)b * LL + l) * TT + t) * HH + h] = g_x[idx];
}

__global__ void aw_kernel(float* __restrict__ out_ws) {
    long idx = (long)blockIdx.x * blockDim.x + threadIdx.x;
    int s = (int)(idx % SS);
    long bt = idx / SS;
    int t = (int)(bt % TT);
    int b = (int)(bt / TT);
    float acc = 0.f;
    #pragma unroll
    for (int h = 0; h < NHH; h++) {
        size_t o = (((size_t)(b * NHH + h)) * TT + t) * SS + s;
        acc += __bfloat162float(g_sch[o]) + __bfloat162float(g_scl[o]);
    }
    out_ws[idx] = acc * (1.0f / NHH);
}

__global__ void wt_kernel(const float* __restrict__ Wt1, const float* __restrict__ Wt2) {
    __shared__ float red[256];
    int i = blockIdx.x;
    float s = 0.f;
    for (int j = threadIdx.x; j < HH; j += 256)
        s += Wt1[(long)i * HH + j] * Wt2[j];
    float tot = block_reduce_sum(s, red);
    if (threadIdx.x == 0) g_wt[i] = tot;
}

__global__ void p_kernel(const float* __restrict__ X, float* __restrict__ outp) {
    __shared__ float red[256];
    long row = blockIdx.x;
    const float* xr = X + row * HH;
    float s = 0.f;
    for (int i = threadIdx.x; i < HH; i += 256) s += xr[i] * g_wt[i];
    float tot = block_reduce_sum(s, red);
    if (threadIdx.x == 0) outp[row] = 1.0f / (1.0f + expf(-tot));
}

// ---------------- driver ----------------
extern "C" void kernel_launch(void* const* d_in, const int* in_sizes, int n_in,
                              void* d_out, int out_size) {
    const int*            tgt      = (const int*)d_in[0];
    const unsigned char*  src_pad  = (const unsigned char*)d_in[1];
    const unsigned char*  tgt_pad  = (const unsigned char*)d_in[2];
    const float*          enc_out  = (const float*)d_in[3];
    const float*          emb      = (const float*)d_in[4];
    const float*          Wq_self  = (const float*)d_in[5];
    const float*          Wk_self  = (const float*)d_in[6];
    const float*          Wv_self  = (const float*)d_in[7];
    const float*          Wo_self  = (const float*)d_in[8];
    const float*          bo_self  = (const float*)d_in[9];
    const float*          Wq_src   = (const float*)d_in[10];
    const float*          Wk_src   = (const float*)d_in[11];
    const float*          Wv_src   = (const float*)d_in[12];
    const float*          Wo_src   = (const float*)d_in[13];
    const float*          bo_src   = (const float*)d_in[14];
    const float*          W1       = (const float*)d_in[15];
    const float*          W2       = (const float*)d_in[16];
    const float*          ln_g     = (const float*)d_in[17];
    const float*          ln_b     = (const float*)d_in[18];
    const float*          final_g  = (const float*)d_in[19];
    const float*          final_b  = (const float*)d_in[20];
    const float*          Wt1      = (const float*)d_in[21];
    const float*          Wt2      = (const float*)d_in[22];

    float* out    = (float*)d_out;
    float* out_r1 = out;
    float* out_r2 = out + (size_t)BB * TT * HH;
    float* out_p  = out_r2 + (size_t)BB * LL * TT * HH;
    float* out_ws = out_p + (size_t)BB * TT;

    static bool attr_done = false;
    if (!attr_done) {
        cudaFuncSetAttribute(gemm_bf, cudaFuncAttributeMaxDynamicSharedMemorySize, 75776);
        cudaFuncSetAttribute(scores_bf, cudaFuncAttributeMaxDynamicSharedMemorySize, 73728);
        cudaFuncSetAttribute(ctx_bf, cudaFuncAttributeMaxDynamicSharedMemorySize, 59392);
        attr_done = true;
    }

    float *x, *sc, *wtv;
    __nv_bfloat16 *wbh, *wbl, *eh, *el, *hh, *hl, *qh, *ql, *kh, *kl, *vh, *vl, *ch, *cl, *fh, *fl, *sch, *scl;
    cudaGetSymbolAddress((void**)&x, g_x);
    cudaGetSymbolAddress((void**)&sc, g_scores);
    cudaGetSymbolAddress((void**)&wtv, g_wt);
    cudaGetSymbolAddress((void**)&wbh, g_wbh);
    cudaGetSymbolAddress((void**)&wbl, g_wbl);
    cudaGetSymbolAddress((void**)&eh, g_eh);
    cudaGetSymbolAddress((void**)&el, g_el);
    cudaGetSymbolAddress((void**)&hh, g_hh);
    cudaGetSymbolAddress((void**)&hl, g_hl);
    cudaGetSymbolAddress((void**)&qh, g_qh);
    cudaGetSymbolAddress((void**)&ql, g_ql);
    cudaGetSymbolAddress((void**)&kh, g_kh);
    cudaGetSymbolAddress((void**)&kl, g_kl);
    cudaGetSymbolAddress((void**)&vh, g_vh);
    cudaGetSymbolAddress((void**)&vl, g_vl);
    cudaGetSymbolAddress((void**)&ch, g_ch);
    cudaGetSymbolAddress((void**)&cl, g_cl);
    cudaGetSymbolAddress((void**)&fh, g_fh);
    cudaGetSymbolAddress((void**)&fl, g_fl);
    cudaGetSymbolAddress((void**)&sch, g_sch);
    cudaGetSymbolAddress((void**)&scl, g_scl);

    const int MT = BB * TT;   // 2048
    const int MS = BB * SS;   // 4096
    const long HL2 = (long)LL * HH * HH;       // 6291456
    const long HF = (long)LL * HH * FF;        // 25165824

    // split all weights + enc_out
    split_kernel<<<HL2 / 1024, 256>>>(Wq_self, wbh + OFF_WQS, wbl + OFF_WQS, HL2);
    split_kernel<<<HL2 / 1024, 256>>>(Wk_self, wbh + OFF_WKS, wbl + OFF_WKS, HL2);
    split_kernel<<<HL2 / 1024, 256>>>(Wv_self, wbh + OFF_WVS, wbl + OFF_WVS, HL2);
    split_kernel<<<HL2 / 1024, 256>>>(Wo_self, wbh + OFF_WOS, wbl + OFF_WOS, HL2);
    split_kernel<<<HL2 / 1024, 256>>>(Wq_src, wbh + OFF_WQX, wbl + OFF_WQX, HL2);
    split_kernel<<<HL2 / 1024, 256>>>(Wk_src, wbh + OFF_WKX, wbl + OFF_WKX, HL2);
    split_kernel<<<HL2 / 1024, 256>>>(Wv_src, wbh + OFF_WVX, wbl + OFF_WVX, HL2);
    split_kernel<<<HL2 / 1024, 256>>>(Wo_src, wbh + OFF_WOX, wbl + OFF_WOX, HL2);
    split_kernel<<<HF / 1024, 256>>>(W1, wbh + OFF_W1, wbl + OFF_W1, HF);
    split_kernel<<<HF / 1024, 256>>>(W2, wbh + OFF_W2, wbl + OFF_W2, HF);
    split_kernel<<<(long)BB * SS * HH / 1024, 256>>>(enc_out, eh, el, (long)BB * SS * HH);

    invfreq_kernel<<<4, 256>>>();
    pe_kernel<<<TT * HH / 256, 256>>>();
    embed_kernel<<<BB * TT * HH / 256, 256>>>(tgt, emb);
    wt_kernel<<<HH, 256>>>(Wt1, Wt2);

    for (int l = 0; l < LL; l++) {
        save_kernel<<<BB * TT * HH / 256, 256>>>(out_r2, l);

        // --- self attention ---
        ln_kernel<<<MT, 256>>>(x, ln_g + (size_t)(l * 3 + 0) * HH, ln_b + (size_t)(l * 3 + 0) * HH, nullptr, hh, hl);
        gemm_bf<<<dim3(HH / 128, MT / 128), 256, 75776>>>(hh, hl, wbh + OFF_WQS + (size_t)l * HH * HH, wbl + OFF_WQS + (size_t)l * HH * HH, nullptr, nullptr, nullptr, qh, ql, MT, HH, HH, 8);
        gemm_bf<<<dim3(HH / 128, MT / 128), 256, 75776>>>(hh, hl, wbh + OFF_WKS + (size_t)l * HH * HH, wbl + OFF_WKS + (size_t)l * HH * HH, nullptr, nullptr, nullptr, kh, kl, MT, HH, HH, 8);
        gemm_bf<<<dim3(HH / 128, MT / 128), 256, 75776>>>(hh, hl, wbh + OFF_WVS + (size_t)l * HH * HH, wbl + OFF_WVS + (size_t)l * HH * HH, nullptr, nullptr, nullptr, vh, vl, MT, HH, HH, 8);
        scores_bf<<<dim3(TT / 128, TT / 128, BB * NHH), 256, 73728>>>(qh, ql, kh, kl, sc, tgt_pad, TT, TT, 1);
        softmax_kernel<<<BB * NHH * TT, 256>>>(sc, sch, scl, TT);
        ctx_bf<<<dim3(1, TT / 128, BB * NHH), 256, 59392>>>(sch, scl, vh, vl, ch, cl, TT, TT);
        gemm_bf<<<dim3(HH / 128, MT / 128), 256, 75776>>>(ch, cl, wbh + OFF_WOS + (size_t)l * HH * HH, wbl + OFF_WOS + (size_t)l * HH * HH, bo_self + (size_t)l * HH, x, x, nullptr, nullptr, MT, HH, HH, 3);

        // --- cross attention ---
        ln_kernel<<<MT, 256>>>(x, ln_g + (size_t)(l * 3 + 1) * HH, ln_b + (size_t)(l * 3 + 1) * HH, nullptr, hh, hl);
        gemm_bf<<<dim3(HH / 128, MT / 128), 256, 75776>>>(hh, hl, wbh + OFF_WQX + (size_t)l * HH * HH, wbl + OFF_WQX + (size_t)l * HH * HH, nullptr, nullptr, nullptr, qh, ql, MT, HH, HH, 8);
        gemm_bf<<<dim3(HH / 128, MS / 128), 256, 75776>>>(eh, el, wbh + OFF_WKX + (size_t)l * HH * HH, wbl + OFF_WKX + (size_t)l * HH * HH, nullptr, nullptr, nullptr, kh, kl, MS, HH, HH, 8);
        gemm_bf<<<dim3(HH / 128, MS / 128), 256, 75776>>>(eh, el, wbh + OFF_WVX + (size_t)l * HH * HH, wbl + OFF_WVX + (size_t)l * HH * HH, nullptr, nullptr, nullptr, vh, vl, MS, HH, HH, 8);
        scores_bf<<<dim3(SS / 128, TT / 128, BB * NHH), 256, 73728>>>(qh, ql, kh, kl, sc, src_pad, TT, SS, 0);
        softmax_kernel<<<BB * NHH * TT, 256>>>(sc, sch, scl, SS);
        if (l == LL - 1)
            aw_kernel<<<BB * TT * SS / 256, 256>>>(out_ws);
        ctx_bf<<<dim3(1, TT / 128, BB * NHH), 256, 59392>>>(sch, scl, vh, vl, ch, cl, TT, SS);
        gemm_bf<<<dim3(HH / 128, MT / 128), 256, 75776>>>(ch, cl, wbh + OFF_WOX + (size_t)l * HH * HH, wbl + OFF_WOX + (size_t)l * HH * HH, bo_src + (size_t)l * HH, x, x, nullptr, nullptr, MT, HH, HH, 3);

        // --- feed forward ---
        ln_kernel<<<MT, 256>>>(x, ln_g + (size_t)(l * 3 + 2) * HH, ln_b + (size_t)(l * 3 + 2) * HH, nullptr, hh, hl);
        gemm_bf<<<dim3(FF / 128, MT / 128), 256, 75776>>>(hh, hl, wbh + OFF_W1 + (size_t)l * HH * FF, wbl + OFF_W1 + (size_t)l * HH * FF, nullptr, nullptr, nullptr, fh, fl, MT, FF, HH, 12);
        gemm_bf<<<dim3(HH / 128, MT / 128), 256, 75776>>>(fh, fl, wbh + OFF_W2 + (size_t)l * FF * HH, wbl + OFF_W2 + (size_t)l * FF * HH, nullptr, x, x, nullptr, nullptr, MT, HH, FF, 2);
    }

    ln_kernel<<<MT, 256>>>(x, final_g, final_b, out_r1, nullptr, nullptr);
    p_kernel<<<MT, 256>>>(x, out_p);
}

// round 5
// speedup vs baseline: 3.8184x; 1.2008x over previous
#include <cuda_runtime.h>
#include <cuda_fp16.h>
#include <math.h>

#define BB 4
#define TT 512
#define SS 1024
#define HH 1024
#define FF 4096
#define NHH 16
#define DHD 64
#define LL 6

// weight hi buffer offsets (elements)
#define OFF_WQS 0
#define OFF_WKS 6291456
#define OFF_WVS 12582912
#define OFF_WOS 18874368
#define OFF_WQX 25165824
#define OFF_WKX 31457280
#define OFF_WVX 37748736
#define OFF_WOX 44040192
#define OFF_W1  50331648
#define OFF_W2  75497472
#define WTOT    100663296

// ---------------- device global scratch ----------------
__device__ __half g_wbh[WTOT];                      // weights hi (B side, [K][N] layout)
__device__ __half g_eh[BB*SS*HH], g_el[BB*SS*HH];   // enc_out hi/lo (A side)
__device__ __half g_hh[BB*TT*HH], g_hl[BB*TT*HH];   // ln out hi/lo
__device__ __half g_qh[BB*TT*HH], g_ql[BB*TT*HH];   // q hi/lo (A of scores)
__device__ __half g_kh[BB*SS*HH];                   // k hi (B of scores)
__device__ __half g_vh[BB*SS*HH];                   // v hi (B of ctx)
__device__ __half g_ch[BB*TT*HH], g_cl[BB*TT*HH];   // ctx hi/lo
__device__ __half g_fh[BB*TT*FF], g_fl[BB*TT*FF];   // ffn mid hi/lo
__device__ __half g_sch[(size_t)BB*NHH*TT*SS], g_scl[(size_t)BB*NHH*TT*SS];
__device__ float g_x[BB*TT*HH];
__device__ float g_scores[(size_t)BB*NHH*TT*SS];
__device__ float g_pe[TT*HH];
__device__ double g_invf[HH];
__device__ float g_wt[HH];

// ---------------- helpers ----------------
__device__ __forceinline__ float block_reduce_sum(float v, float* red) {
    int tid = threadIdx.x;
    red[tid] = v; __syncthreads();
    for (int s = 128; s > 0; s >>= 1) {
        if (tid < s) red[tid] += red[tid + s];
        __syncthreads();
    }
    float r = red[0]; __syncthreads();
    return r;
}

__device__ __forceinline__ void mma16816(float c[4], const unsigned a[4], const unsigned b[2]) {
    asm volatile("mma.sync.aligned.m16n8k16.row.col.f32.f16.f16.f32 "
        "{%0,%1,%2,%3}, {%4,%5,%6,%7}, {%8,%9}, {%0,%1,%2,%3};"
        : "+f"(c[0]), "+f"(c[1]), "+f"(c[2]), "+f"(c[3])
        : "r"(a[0]), "r"(a[1]), "r"(a[2]), "r"(a[3]), "r"(b[0]), "r"(b[1]));
}

__device__ __forceinline__ void ldsm4(unsigned& r0, unsigned& r1, unsigned& r2, unsigned& r3,
                                      const void* p) {
    unsigned a = (unsigned)__cvta_generic_to_shared(p);
    asm volatile("ldmatrix.sync.aligned.m8n8.x4.shared.b16 {%0,%1,%2,%3}, [%4];"
        : "=r"(r0), "=r"(r1), "=r"(r2), "=r"(r3) : "r"(a));
}
__device__ __forceinline__ void ldsm4t(unsigned& r0, unsigned& r1, unsigned& r2, unsigned& r3,
                                       const void* p) {
    unsigned a = (unsigned)__cvta_generic_to_shared(p);
    asm volatile("ldmatrix.sync.aligned.m8n8.x4.trans.shared.b16 {%0,%1,%2,%3}, [%4];"
        : "=r"(r0), "=r"(r1), "=r"(r2), "=r"(r3) : "r"(a));
}

__device__ __forceinline__ void cpa16(void* dst, const void* src) {
    unsigned d = (unsigned)__cvta_generic_to_shared(dst);
    asm volatile("cp.async.ca.shared.global [%0], [%1], 16;" :: "r"(d), "l"(src));
}
#define CP_COMMIT asm volatile("cp.async.commit_group;")
#define CP_WAIT0 asm volatile("cp.async.wait_group 0;")
#define CP_WAIT1 asm volatile("cp.async.wait_group 1;")

__device__ __forceinline__ void split_w2(float v0, float v1, __half* hp, __half* lp) {
    __half h0 = __float2half_rn(v0), h1 = __float2half_rn(v1);
    *(__half2*)hp = __halves2half2(h0, h1);
    *(__half2*)lp = __halves2half2(__float2half_rn(v0 - __half2float(h0)),
                                   __float2half_rn(v1 - __half2float(h1)));
}
__device__ __forceinline__ void store_hi2(float v0, float v1, __half* hp) {
    *(__half2*)hp = __halves2half2(__float2half_rn(v0), __float2half_rn(v1));
}

// ---------------- conversions ----------------
__global__ void split_kernel(const float* __restrict__ src, __half* __restrict__ h,
                             __half* __restrict__ l, long n) {
    long i = ((long)blockIdx.x * blockDim.x + threadIdx.x) * 4;
    if (i < n) {
        float4 v = *(const float4*)(src + i);
        split_w2(v.x, v.y, h + i, l + i);
        split_w2(v.z, v.w, h + i + 2, l + i + 2);
    }
}
__global__ void hisplit_kernel(const float* __restrict__ src, __half* __restrict__ h, long n) {
    long i = ((long)blockIdx.x * blockDim.x + threadIdx.x) * 4;
    if (i < n) {
        float4 v = *(const float4*)(src + i);
        store_hi2(v.x, v.y, h + i);
        store_hi2(v.z, v.w, h + i + 2);
    }
}

// ---------------- embedding / positional ----------------
__global__ void invfreq_kernel() {
    int h = blockIdx.x * blockDim.x + threadIdx.x;
    if (h < HH) {
        double e = (double)(2 * (h / 2)) / (double)HH;
        g_invf[h] = pow(10000.0, -e);
    }
}
__global__ void pe_kernel() {
    int idx = blockIdx.x * blockDim.x + threadIdx.x;
    int t = idx / HH, h = idx % HH;
    double ang = (double)t * g_invf[h];
    g_pe[idx] = (float)((h & 1) ? cos(ang) : sin(ang));
}
__global__ void embed_kernel(const int* __restrict__ tgt, const float* __restrict__ emb) {
    long idx = (long)blockIdx.x * blockDim.x + threadIdx.x;
    int h = (int)(idx % HH);
    long bt = idx / HH;
    int tok = tgt[bt];
    int t = (int)(bt % TT);
    g_x[idx] = emb[(long)tok * HH + h] * 32.0f + g_pe[t * HH + h];
}

// ---------------- layernorm ----------------
__global__ void ln_kernel(const float* __restrict__ X, const float* __restrict__ g,
                          const float* __restrict__ b, float* __restrict__ Yf,
                          __half* __restrict__ Yh, __half* __restrict__ Yl) {
    __shared__ float red[256];
    long row = blockIdx.x;
    const float* x = X + row * HH;
    int tid = threadIdx.x;
    float s = 0.f;
    for (int i = tid; i < HH; i += 256) s += x[i];
    float mean = block_reduce_sum(s, red) * (1.0f / HH);
    float v = 0.f;
    for (int i = tid; i < HH; i += 256) { float d = x[i] - mean; v += d * d; }
    float var = block_reduce_sum(v, red) * (1.0f / HH);
    float inv = 1.0f / sqrtf(var + 1e-6f);
    if (Yf) {
        for (int i = tid; i < HH; i += 256)
            Yf[row * HH + i] = (x[i] - mean) * inv * g[i] + b[i];
    } else {
        for (int i = tid * 2; i < HH; i += 512) {
            float y0 = (x[i] - mean) * inv * g[i] + b[i];
            float y1 = (x[i + 1] - mean) * inv * g[i + 1] + b[i + 1];
            split_w2(y0, y1, Yh + row * HH + i, Yl + row * HH + i);
        }
    }
}

// ======================= pipelined fp16x2 GEMM =======================
// C = A(MxK)@B(KxN); A = Ah+Al, B = Bh. flags: 1 bias, 2 residual, 4 relu, 8 split-out, 16 hi-out
#define APITCH 40
#define BPITCH 136
__global__ void __launch_bounds__(256) gemm_bf(
    const __half* __restrict__ Ah, const __half* __restrict__ Al,
    const __half* __restrict__ Bh,
    const float* __restrict__ bias, const float* __restrict__ res,
    float* __restrict__ Cf, __half* __restrict__ Ch, __half* __restrict__ Cl,
    int M, int N, int K, int flags) {
    extern __shared__ __half sm[];
    __half* sAh = sm;                      // [2][128][APITCH]
    __half* sAl = sAh + 2 * 128 * APITCH;
    __half* sBh = sAl + 2 * 128 * APITCH;  // [2][32][BPITCH]
    int tid = threadIdx.x, lane = tid & 31, wid = tid >> 5;
    int wm = (wid >> 2) * 64, wn = (wid & 3) * 32;
    int m0 = blockIdx.y * 128, n0 = blockIdx.x * 128;
    float acc[4][4][4] = {};

    {
        #pragma unroll
        for (int i = 0; i < 2; i++) {
            int idx = tid + i * 256;
            int r = idx >> 2, c = (idx & 3) * 8;
            cpa16(sAh + r * APITCH + c, Ah + (size_t)(m0 + r) * K + c);
            cpa16(sAl + r * APITCH + c, Al + (size_t)(m0 + r) * K + c);
        }
        #pragma unroll
        for (int i = 0; i < 2; i++) {
            int idx = tid + i * 256;
            int r = idx >> 4, c = (idx & 15) * 8;
            cpa16(sBh + r * BPITCH + c, Bh + (size_t)r * N + n0 + c);
        }
        CP_COMMIT;
    }
    int ntiles = K / 32;
    for (int t = 0; t < ntiles; t++) {
        if (t + 1 < ntiles) {
            int st = (t + 1) & 1, k0 = (t + 1) * 32;
            #pragma unroll
            for (int i = 0; i < 2; i++) {
                int idx = tid + i * 256;
                int r = idx >> 2, c = (idx & 3) * 8;
                cpa16(sAh + st * 128 * APITCH + r * APITCH + c, Ah + (size_t)(m0 + r) * K + k0 + c);
                cpa16(sAl + st * 128 * APITCH + r * APITCH + c, Al + (size_t)(m0 + r) * K + k0 + c);
            }
            #pragma unroll
            for (int i = 0; i < 2; i++) {
                int idx = tid + i * 256;
                int r = idx >> 4, c = (idx & 15) * 8;
                cpa16(sBh + st * 32 * BPITCH + r * BPITCH + c, Bh + (size_t)(k0 + r) * N + n0 + c);
            }
            CP_COMMIT;
            CP_WAIT1;
        } else {
            CP_WAIT0;
        }
        __syncthreads();
        int st = t & 1;
        __half* cAh = sAh + st * 128 * APITCH;
        __half* cAl = sAl + st * 128 * APITCH;
        __half* cBh = sBh + st * 32 * BPITCH;
        #pragma unroll
        for (int ks = 0; ks < 32; ks += 16) {
            unsigned bh[4][2];
            #pragma unroll
            for (int np = 0; np < 2; np++) {
                int r = ks + (lane & 7) + ((lane >> 3) & 1) * 8;
                int c = wn + np * 16 + (lane >> 4) * 8;
                ldsm4t(bh[np*2][0], bh[np*2][1], bh[np*2+1][0], bh[np*2+1][1], cBh + r * BPITCH + c);
            }
            #pragma unroll
            for (int mt = 0; mt < 4; mt++) {
                int r = wm + mt * 16 + (lane & 7) + ((lane >> 3) & 1) * 8;
                int c = ks + (lane >> 4) * 8;
                unsigned ah[4], al[4];
                ldsm4(ah[0], ah[1], ah[2], ah[3], cAh + r * APITCH + c);
                ldsm4(al[0], al[1], al[2], al[3], cAl + r * APITCH + c);
                #pragma unroll
                for (int nt = 0; nt < 4; nt++) {
                    mma16816(acc[mt][nt], ah, bh[nt]);
                    mma16816(acc[mt][nt], al, bh[nt]);
                }
            }
        }
        __syncthreads();
    }
    #pragma unroll
    for (int mt = 0; mt < 4; mt++)
        #pragma unroll
        for (int nt = 0; nt < 4; nt++)
            #pragma unroll
            for (int half = 0; half < 2; half++) {
                int row = m0 + wm + mt * 16 + (lane >> 2) + half * 8;
                int col = n0 + wn + nt * 8 + (lane & 3) * 2;
                float v0 = acc[mt][nt][half * 2], v1 = acc[mt][nt][half * 2 + 1];
                if (flags & 1) { v0 += bias[col]; v1 += bias[col + 1]; }
                if (flags & 2) { float2 rr = *(const float2*)&res[(size_t)row * N + col]; v0 += rr.x; v1 += rr.y; }
                if (flags & 4) { v0 = fmaxf(v0, 0.f); v1 = fmaxf(v1, 0.f); }
                if (flags & 8) split_w2(v0, v1, Ch + (size_t)row * N + col, Cl + (size_t)row * N + col);
                else if (flags & 16) store_hi2(v0, v1, Ch + (size_t)row * N + col);
                else *(float2*)&Cf[(size_t)row * N + col] = make_float2(v0, v1);
            }
}

// ======================= attention scores =======================
#define SPITCH 72
__global__ void __launch_bounds__(256) scores_bf(
    const __half* __restrict__ Qh, const __half* __restrict__ Ql,
    const __half* __restrict__ Kh,
    float* __restrict__ Sout, const unsigned char* __restrict__ pad,
    int Tq, int Tk, int causal) {
    extern __shared__ __half sm[];
    __half* sQh = sm;                  // [128][SPITCH]
    __half* sQl = sQh + 128 * SPITCH;
    __half* sKh = sQl + 128 * SPITCH;
    int tid = threadIdx.x, lane = tid & 31, wid = tid >> 5;
    int wm = (wid >> 2) * 64, wn = (wid & 3) * 32;
    int bh = blockIdx.z, b = bh >> 4, h = bh & 15;
    int t0 = blockIdx.y * 128, s0 = blockIdx.x * 128;
    const __half* Qbh = Qh + ((size_t)(b * Tq + t0)) * HH + h * DHD;
    const __half* Qbl = Ql + ((size_t)(b * Tq + t0)) * HH + h * DHD;
    const __half* Kbh = Kh + ((size_t)(b * Tk + s0)) * HH + h * DHD;
    #pragma unroll
    for (int i = 0; i < 4; i++) {
        int idx = tid + i * 256;
        int r = idx >> 3, c = (idx & 7) * 8;
        cpa16(sQh + r * SPITCH + c, Qbh + (size_t)r * HH + c);
        cpa16(sQl + r * SPITCH + c, Qbl + (size_t)r * HH + c);
        cpa16(sKh + r * SPITCH + c, Kbh + (size_t)r * HH + c);
    }
    CP_COMMIT; CP_WAIT0;
    __syncthreads();
    float acc[4][4][4] = {};
    #pragma unroll
    for (int ks = 0; ks < 64; ks += 16) {
        unsigned bhf[4][2];
        #pragma unroll
        for (int np = 0; np < 2; np++) {
            int r = wn + np * 16 + (lane & 7) + (lane >> 4) * 8;
            int c = ks + ((lane >> 3) & 1) * 8;
            ldsm4(bhf[np*2][0], bhf[np*2][1], bhf[np*2+1][0], bhf[np*2+1][1], sKh + r * SPITCH + c);
        }
        #pragma unroll
        for (int mt = 0; mt < 4; mt++) {
            int r = wm + mt * 16 + (lane & 7) + ((lane >> 3) & 1) * 8;
            int c = ks + (lane >> 4) * 8;
            unsigned ah[4], al[4];
            ldsm4(ah[0], ah[1], ah[2], ah[3], sQh + r * SPITCH + c);
            ldsm4(al[0], al[1], al[2], al[3], sQl + r * SPITCH + c);
            #pragma unroll
            for (int nt = 0; nt < 4; nt++) {
                mma16816(acc[mt][nt], ah, bhf[nt]);
                mma16816(acc[mt][nt], al, bhf[nt]);
            }
        }
    }
    #pragma unroll
    for (int mt = 0; mt < 4; mt++)
        #pragma unroll
        for (int nt = 0; nt < 4; nt++)
            #pragma unroll
            for (int i = 0; i < 4; i++) {
                int t = t0 + wm + mt * 16 + (lane >> 2) + ((i >> 1) ? 8 : 0);
                int s = s0 + wn + nt * 8 + (lane & 3) * 2 + (i & 1);
                float v = acc[mt][nt][i] * 0.125f;
                bool m = (causal && (s > t)) || (pad[(size_t)b * Tk + s] != 0);
                Sout[((size_t)bh * Tq + t) * Tk + s] = m ? -1e18f : v;
            }
}

// ======================= ctx = softmax @ V =======================
#define VPITCH 72
__global__ void __launch_bounds__(256) ctx_bf(
    const __half* __restrict__ Wh, const __half* __restrict__ Wl,
    const __half* __restrict__ Vh,
    __half* __restrict__ Ch, __half* __restrict__ Cl, int Tq, int Tk) {
    extern __shared__ __half sm[];
    __half* sAh = sm;                      // [2][128][APITCH]
    __half* sAl = sAh + 2 * 128 * APITCH;
    __half* sBh = sAl + 2 * 128 * APITCH;  // [2][32][VPITCH]
    int tid = threadIdx.x, lane = tid & 31, wid = tid >> 5;
    int wm = (wid >> 1) * 32, wn = (wid & 1) * 32;
    int bh = blockIdx.z, b = bh >> 4, h = bh & 15;
    int t0 = blockIdx.y * 128;
    const __half* Abh = Wh + ((size_t)bh * Tq + t0) * Tk;
    const __half* Abl = Wl + ((size_t)bh * Tq + t0) * Tk;
    const __half* Bbh = Vh + (size_t)b * Tk * HH + h * DHD;
    float acc[2][4][4] = {};
    {
        #pragma unroll
        for (int i = 0; i < 2; i++) {
            int idx = tid + i * 256;
            int r = idx >> 2, c = (idx & 3) * 8;
            cpa16(sAh + r * APITCH + c, Abh + (size_t)r * Tk + c);
            cpa16(sAl + r * APITCH + c, Abl + (size_t)r * Tk + c);
        }
        {
            int r = tid >> 3, c = (tid & 7) * 8;
            cpa16(sBh + r * VPITCH + c, Bbh + (size_t)r * HH + c);
        }
        CP_COMMIT;
    }
    int ntiles = Tk / 32;
    for (int t = 0; t < ntiles; t++) {
        if (t + 1 < ntiles) {
            int st = (t + 1) & 1, k0 = (t + 1) * 32;
            #pragma unroll
            for (int i = 0; i < 2; i++) {
                int idx = tid + i * 256;
                int r = idx >> 2, c = (idx & 3) * 8;
                cpa16(sAh + st * 128 * APITCH + r * APITCH + c, Abh + (size_t)r * Tk + k0 + c);
                cpa16(sAl + st * 128 * APITCH + r * APITCH + c, Abl + (size_t)r * Tk + k0 + c);
            }
            {
                int r = tid >> 3, c = (tid & 7) * 8;
                cpa16(sBh + st * 32 * VPITCH + r * VPITCH + c, Bbh + (size_t)(k0 + r) * HH + c);
            }
            CP_COMMIT;
            CP_WAIT1;
        } else {
            CP_WAIT0;
        }
        __syncthreads();
        int st = t & 1;
        __half* cAh = sAh + st * 128 * APITCH;
        __half* cAl = sAl + st * 128 * APITCH;
        __half* cBh = sBh + st * 32 * VPITCH;
        #pragma unroll
        for (int ks = 0; ks < 32; ks += 16) {
            unsigned bhf[4][2];
            #pragma unroll
            for (int np = 0; np < 2; np++) {
                int r = ks + (lane & 7) + ((lane >> 3) & 1) * 8;
                int c = wn + np * 16 + (lane >> 4) * 8;
                ldsm4t(bhf[np*2][0], bhf[np*2][1], bhf[np*2+1][0], bhf[np*2+1][1], cBh + r * VPITCH + c);
            }
            #pragma unroll
            for (int mt = 0; mt < 2; mt++) {
                int r = wm + mt * 16 + (lane & 7) + ((lane >> 3) & 1) * 8;
                int c = ks + (lane >> 4) * 8;
                unsigned ah[4], al[4];
                ldsm4(ah[0], ah[1], ah[2], ah[3], cAh + r * APITCH + c);
                ldsm4(al[0], al[1], al[2], al[3], cAl + r * APITCH + c);
                #pragma unroll
                for (int nt = 0; nt < 4; nt++) {
                    mma16816(acc[mt][nt], ah, bhf[nt]);
                    mma16816(acc[mt][nt], al, bhf[nt]);
                }
            }
        }
        __syncthreads();
    }
    #pragma unroll
    for (int mt = 0; mt < 2; mt++)
        #pragma unroll
        for (int nt = 0; nt < 4; nt++)
            #pragma unroll
            for (int half = 0; half < 2; half++) {
                int t = t0 + wm + mt * 16 + (lane >> 2) + half * 8;
                int d = wn + nt * 8 + (lane & 3) * 2;
                size_t o = ((size_t)(b * Tq) + t) * HH + h * DHD + d;
                split_w2(acc[mt][nt][half * 2], acc[mt][nt][half * 2 + 1], Ch + o, Cl + o);
            }
}

// ---------------- softmax ----------------
__global__ void softmax_kernel(const float* __restrict__ Sc, __half* __restrict__ Oh,
                               __half* __restrict__ Ol, int Tk) {
    __shared__ float red[256];
    long row = blockIdx.x;
    const float* p = Sc + row * Tk;
    int tid = threadIdx.x;
    float mx = -3.0e38f;
    for (int i = tid; i < Tk; i += 256) mx = fmaxf(mx, p[i]);
    red[tid] = mx; __syncthreads();
    for (int s = 128; s > 0; s >>= 1) {
        if (tid < s) red[tid] = fmaxf(red[tid], red[tid + s]);
        __syncthreads();
    }
    mx = red[0]; __syncthreads();
    float sum = 0.f;
    for (int i = tid; i < Tk; i += 256) sum += expf(p[i] - mx);
    float tot = block_reduce_sum(sum, red);
    float inv = 1.0f / tot;
    for (int i = tid * 2; i < Tk; i += 512) {
        float e0 = expf(p[i] - mx) * inv;
        float e1 = expf(p[i + 1] - mx) * inv;
        split_w2(e0, e1, Oh + row * Tk + i, Ol + row * Tk + i);
    }
}

// ---------------- misc ----------------
__global__ void save_kernel(float* __restrict__ out_r2, int l) {
    long idx = (long)blockIdx.x * blockDim.x + threadIdx.x;
    int h = (int)(idx % HH);
    long bt = idx / HH;
    int t = (int)(bt % TT);
    int b = (int)(bt / TT);
    out_r2[(((long)b * LL + l) * TT + t) * HH + h] = g_x[idx];
}

__global__ void aw_kernel(float* __restrict__ out_ws) {
    long idx = (long)blockIdx.x * blockDim.x + threadIdx.x;
    int s = (int)(idx % SS);
    long bt = idx / SS;
    int t = (int)(bt % TT);
    int b = (int)(bt / TT);
    float acc = 0.f;
    #pragma unroll
    for (int h = 0; h < NHH; h++) {
        size_t o = (((size_t)(b * NHH + h)) * TT + t) * SS + s;
        acc += __half2float(g_sch[o]) + __half2float(g_scl[o]);
    }
    out_ws[idx] = acc * (1.0f / NHH);
}

__global__ void wt_kernel(const float* __restrict__ Wt1, const float* __restrict__ Wt2) {
    __shared__ float red[256];
    int i = blockIdx.x;
    float s = 0.f;
    for (int j = threadIdx.x; j < HH; j += 256)
        s += Wt1[(long)i * HH + j] * Wt2[j];
    float tot = block_reduce_sum(s, red);
    if (threadIdx.x == 0) g_wt[i] = tot;
}

__global__ void p_kernel(const float* __restrict__ X, float* __restrict__ outp) {
    __shared__ float red[256];
    long row = blockIdx.x;
    const float* xr = X + row * HH;
    float s = 0.f;
    for (int i = threadIdx.x; i < HH; i += 256) s += xr[i] * g_wt[i];
    float tot = block_reduce_sum(s, red);
    if (threadIdx.x == 0) outp[row] = 1.0f / (1.0f + expf(-tot));
}

// ---------------- driver ----------------
extern "C" void kernel_launch(void* const* d_in, const int* in_sizes, int n_in,
                              void* d_out, int out_size) {
    const int*            tgt      = (const int*)d_in[0];
    const unsigned char*  src_pad  = (const unsigned char*)d_in[1];
    const unsigned char*  tgt_pad  = (const unsigned char*)d_in[2];
    const float*          enc_out  = (const float*)d_in[3];
    const float*          emb      = (const float*)d_in[4];
    const float*          Wq_self  = (const float*)d_in[5];
    const float*          Wk_self  = (const float*)d_in[6];
    const float*          Wv_self  = (const float*)d_in[7];
    const float*          Wo_self  = (const float*)d_in[8];
    const float*          bo_self  = (const float*)d_in[9];
    const float*          Wq_src   = (const float*)d_in[10];
    const float*          Wk_src   = (const float*)d_in[11];
    const float*          Wv_src   = (const float*)d_in[12];
    const float*          Wo_src   = (const float*)d_in[13];
    const float*          bo_src   = (const float*)d_in[14];
    const float*          W1       = (const float*)d_in[15];
    const float*          W2       = (const float*)d_in[16];
    const float*          ln_g     = (const float*)d_in[17];
    const float*          ln_b     = (const float*)d_in[18];
    const float*          final_g  = (const float*)d_in[19];
    const float*          final_b  = (const float*)d_in[20];
    const float*          Wt1      = (const float*)d_in[21];
    const float*          Wt2      = (const float*)d_in[22];

    float* out    = (float*)d_out;
    float* out_r1 = out;
    float* out_r2 = out + (size_t)BB * TT * HH;
    float* out_p  = out_r2 + (size_t)BB * LL * TT * HH;
    float* out_ws = out_p + (size_t)BB * TT;

    static bool attr_done = false;
    if (!attr_done) {
        cudaFuncSetAttribute(gemm_bf, cudaFuncAttributeMaxDynamicSharedMemorySize, 58368);
        cudaFuncSetAttribute(scores_bf, cudaFuncAttributeMaxDynamicSharedMemorySize, 55296);
        cudaFuncSetAttribute(ctx_bf, cudaFuncAttributeMaxDynamicSharedMemorySize, 50176);
        attr_done = true;
    }

    float *x, *sc;
    __half *wbh, *eh, *el, *hh, *hl, *qh, *ql, *kh, *vh, *ch, *cl, *fh, *fl, *sch, *scl;
    cudaGetSymbolAddress((void**)&x, g_x);
    cudaGetSymbolAddress((void**)&sc, g_scores);
    cudaGetSymbolAddress((void**)&wbh, g_wbh);
    cudaGetSymbolAddress((void**)&eh, g_eh);
    cudaGetSymbolAddress((void**)&el, g_el);
    cudaGetSymbolAddress((void**)&hh, g_hh);
    cudaGetSymbolAddress((void**)&hl, g_hl);
    cudaGetSymbolAddress((void**)&qh, g_qh);
    cudaGetSymbolAddress((void**)&ql, g_ql);
    cudaGetSymbolAddress((void**)&kh, g_kh);
    cudaGetSymbolAddress((void**)&vh, g_vh);
    cudaGetSymbolAddress((void**)&ch, g_ch);
    cudaGetSymbolAddress((void**)&cl, g_cl);
    cudaGetSymbolAddress((void**)&fh, g_fh);
    cudaGetSymbolAddress((void**)&fl, g_fl);
    cudaGetSymbolAddress((void**)&sch, g_sch);
    cudaGetSymbolAddress((void**)&scl, g_scl);

    const int MT = BB * TT;   // 2048
    const int MS = BB * SS;   // 4096
    const long HL2 = (long)LL * HH * HH;
    const long HF = (long)LL * HH * FF;

    // weights: hi-only conversion (B operands)
    hisplit_kernel<<<HL2 / 1024, 256>>>(Wq_self, wbh + OFF_WQS, HL2);
    hisplit_kernel<<<HL2 / 1024, 256>>>(Wk_self, wbh + OFF_WKS, HL2);
    hisplit_kernel<<<HL2 / 1024, 256>>>(Wv_self, wbh + OFF_WVS, HL2);
    hisplit_kernel<<<HL2 / 1024, 256>>>(Wo_self, wbh + OFF_WOS, HL2);
    hisplit_kernel<<<HL2 / 1024, 256>>>(Wq_src, wbh + OFF_WQX, HL2);
    hisplit_kernel<<<HL2 / 1024, 256>>>(Wk_src, wbh + OFF_WKX, HL2);
    hisplit_kernel<<<HL2 / 1024, 256>>>(Wv_src, wbh + OFF_WVX, HL2);
    hisplit_kernel<<<HL2 / 1024, 256>>>(Wo_src, wbh + OFF_WOX, HL2);
    hisplit_kernel<<<HF / 1024, 256>>>(W1, wbh + OFF_W1, HF);
    hisplit_kernel<<<HF / 1024, 256>>>(W2, wbh + OFF_W2, HF);
    split_kernel<<<(long)BB * SS * HH / 1024, 256>>>(enc_out, eh, el, (long)BB * SS * HH);

    invfreq_kernel<<<4, 256>>>();
    pe_kernel<<<TT * HH / 256, 256>>>();
    embed_kernel<<<BB * TT * HH / 256, 256>>>(tgt, emb);
    wt_kernel<<<HH, 256>>>(Wt1, Wt2);

    for (int l = 0; l < LL; l++) {
        save_kernel<<<BB * TT * HH / 256, 256>>>(out_r2, l);

        // --- self attention ---
        ln_kernel<<<MT, 256>>>(x, ln_g + (size_t)(l * 3 + 0) * HH, ln_b + (size_t)(l * 3 + 0) * HH, nullptr, hh, hl);
        gemm_bf<<<dim3(HH / 128, MT / 128), 256, 58368>>>(hh, hl, wbh + OFF_WQS + (size_t)l * HH * HH, nullptr, nullptr, nullptr, qh, ql, MT, HH, HH, 8);
        gemm_bf<<<dim3(HH / 128, MT / 128), 256, 58368>>>(hh, hl, wbh + OFF_WKS + (size_t)l * HH * HH, nullptr, nullptr, nullptr, kh, nullptr, MT, HH, HH, 16);
        gemm_bf<<<dim3(HH / 128, MT / 128), 256, 58368>>>(hh, hl, wbh + OFF_WVS + (size_t)l * HH * HH, nullptr, nullptr, nullptr, vh, nullptr, MT, HH, HH, 16);
        scores_bf<<<dim3(TT / 128, TT / 128, BB * NHH), 256, 55296>>>(qh, ql, kh, sc, tgt_pad, TT, TT, 1);
        softmax_kernel<<<BB * NHH * TT, 256>>>(sc, sch, scl, TT);
        ctx_bf<<<dim3(1, TT / 128, BB * NHH), 256, 50176>>>(sch, scl, vh, ch, cl, TT, TT);
        gemm_bf<<<dim3(HH / 128, MT / 128), 256, 58368>>>(ch, cl, wbh + OFF_WOS + (size_t)l * HH * HH, bo_self + (size_t)l * HH, x, x, nullptr, nullptr, MT, HH, HH, 3);

        // --- cross attention ---
        ln_kernel<<<MT, 256>>>(x, ln_g + (size_t)(l * 3 + 1) * HH, ln_b + (size_t)(l * 3 + 1) * HH, nullptr, hh, hl);
        gemm_bf<<<dim3(HH / 128, MT / 128), 256, 58368>>>(hh, hl, wbh + OFF_WQX + (size_t)l * HH * HH, nullptr, nullptr, nullptr, qh, ql, MT, HH, HH, 8);
        gemm_bf<<<dim3(HH / 128, MS / 128), 256, 58368>>>(eh, el, wbh + OFF_WKX + (size_t)l * HH * HH, nullptr, nullptr, nullptr, kh, nullptr, MS, HH, HH, 16);
        gemm_bf<<<dim3(HH / 128, MS / 128), 256, 58368>>>(eh, el, wbh + OFF_WVX + (size_t)l * HH * HH, nullptr, nullptr, nullptr, vh, nullptr, MS, HH, HH, 16);
        scores_bf<<<dim3(SS / 128, TT / 128, BB * NHH), 256, 55296>>>(qh, ql, kh, sc, src_pad, TT, SS, 0);
        softmax_kernel<<<BB * NHH * TT, 256>>>(sc, sch, scl, SS);
        if (l == LL - 1)
            aw_kernel<<<BB * TT * SS / 256, 256>>>(out_ws);
        ctx_bf<<<dim3(1, TT / 128, BB * NHH), 256, 50176>>>(sch, scl, vh, ch, cl, TT, SS);
        gemm_bf<<<dim3(HH / 128, MT / 128), 256, 58368>>>(ch, cl, wbh + OFF_WOX + (size_t)l * HH * HH, bo_src + (size_t)l * HH, x, x, nullptr, nullptr, MT, HH, HH, 3);

        // --- feed forward ---
        ln_kernel<<<MT, 256>>>(x, ln_g + (size_t)(l * 3 + 2) * HH, ln_b + (size_t)(l * 3 + 2) * HH, nullptr, hh, hl);
        gemm_bf<<<dim3(FF / 128, MT / 128), 256, 58368>>>(hh, hl, wbh + OFF_W1 + (size_t)l * HH * FF, nullptr, nullptr, nullptr, fh, fl, MT, FF, HH, 12);
        gemm_bf<<<dim3(HH / 128, MT / 128), 256, 58368>>>(fh, fl, wbh + OFF_W2 + (size_t)l * FF * HH, nullptr, x, x, nullptr, nullptr, MT, HH, FF, 2);
    }

    ln_kernel<<<MT, 256>>>(x, final_g, final_b, out_r1, nullptr, nullptr);
    p_kernel<<<MT, 256>>>(x, out_p);
}